// round 14
// baseline (speedup 1.0000x reference)
#include <cuda_runtime.h>
#include <cuda_fp16.h>
#include <math.h>
#include <stdint.h>

#define BATCH 2
#define CCH   512
#define NTOK  4096
#define GRP   32
#define CPG   (CCH / GRP)
#define EPSV  1e-6f

// fp32-acc GEMM tiling (QKV / proj)
#define BM 128
#define BN 256
#define BK 128
#define A_BYTES (BM * BK * 2)          // 32768
#define B_BYTES (BN * BK * 2)          // 65536
#define STAGE_BYTES (A_BYTES + B_BYTES)
#define DSMEM (2 * STAGE_BYTES)        // 196608

// fp16-acc GEMM tiling (S / PV): CTA 128x128x64, 4 warps, 2 CTAs/SM
#define SBM 128
#define SBN 128
#define SBK 64
#define SA_BYTES (SBM * SBK * 2)        // 16384
#define SB_BYTES (SBN * SBK * 2)        // 16384
#define SSTAGE (SA_BYTES + SB_BYTES)    // 32768
#define DSMEM_S (3 * SSTAGE)            // 98304

// -------- scratch (__device__ globals; no allocation allowed) --------
__device__ __half g_hn[(size_t)BATCH * NTOK * CCH];   // GN out, TRANSPOSED [b, n, c]
__device__ __half g_q [(size_t)BATCH * NTOK * CCH];   // [b, n, c]  (pre-scaled by att_scale)
__device__ __half g_k [(size_t)BATCH * NTOK * CCH];   // [b, n, c]
__device__ __half g_vt[(size_t)BATCH * CCH * NTOK];   // V TRANSPOSED [b, c, n]
__device__ __half g_o [(size_t)BATCH * NTOK * CCH];   // [b, n, c]
__device__ __half g_p [(size_t)BATCH * NTOK * NTOK];  // scores -> probs (fp16, in-place)
__device__ __half g_w16[4 * (size_t)CCH * CCH];       // wq, wk, wv, wo in fp16

// ---------------- helpers ----------------
__device__ __forceinline__ uint32_t smem_u32(const void* p) {
    uint32_t a;
    asm("{ .reg .u64 t; cvta.to.shared.u64 t, %1; cvt.u32.u64 %0, t; }"
        : "=r"(a) : "l"(p));
    return a;
}
__device__ __forceinline__ void cp16(void* dst, const void* src) {
    uint32_t d = smem_u32(dst);
    asm volatile("cp.async.cg.shared.global [%0], [%1], 16;" :: "r"(d), "l"(src));
}
#define CP_COMMIT() asm volatile("cp.async.commit_group;")

#define LDSM4(r0, r1, r2, r3, addr) \
    asm volatile("ldmatrix.sync.aligned.m8n8.x4.shared.b16 {%0,%1,%2,%3}, [%4];" \
        : "=r"(r0), "=r"(r1), "=r"(r2), "=r"(r3) : "r"(addr))

__device__ __forceinline__ void mma_f16(float* d, const uint32_t* a, const uint32_t* b) {
    asm volatile(
        "mma.sync.aligned.m16n8k16.row.col.f32.f16.f16.f32 "
        "{%0,%1,%2,%3},{%4,%5,%6,%7},{%8,%9},{%0,%1,%2,%3};"
        : "+f"(d[0]), "+f"(d[1]), "+f"(d[2]), "+f"(d[3])
        : "r"(a[0]), "r"(a[1]), "r"(a[2]), "r"(a[3]), "r"(b[0]), "r"(b[1]));
}

// fp16-accumulator variant
__device__ __forceinline__ void mma_f16a(uint32_t* d, const uint32_t* a, const uint32_t* b) {
    asm volatile(
        "mma.sync.aligned.m16n8k16.row.col.f16.f16.f16.f16 "
        "{%0,%1},{%2,%3,%4,%5},{%6,%7},{%0,%1};"
        : "+r"(d[0]), "+r"(d[1])
        : "r"(a[0]), "r"(a[1]), "r"(a[2]), "r"(a[3]), "r"(b[0]), "r"(b[1]));
}

__device__ __forceinline__ uint32_t h2_bits(__half2 h) {
    uint32_t u;
    memcpy(&u, &h, 4);
    return u;
}

// ---------------------------------------------------------------
// Weight conversion fp32 -> fp16
// ---------------------------------------------------------------
__global__ void convw_kernel(const float* __restrict__ a, const float* __restrict__ b,
                             const float* __restrict__ c, const float* __restrict__ d)
{
    const float* srcs[4] = {a, b, c, d};
    const float* src = srcs[blockIdx.y];
    __half* dst = g_w16 + (size_t)blockIdx.y * CCH * CCH;
    int i = (blockIdx.x * 256 + threadIdx.x) * 4;
    float4 v = *reinterpret_cast<const float4*>(&src[i]);
    *reinterpret_cast<__half2*>(&dst[i])     = __floats2half2_rn(v.x, v.y);
    *reinterpret_cast<__half2*>(&dst[i + 2]) = __floats2half2_rn(v.z, v.w);
}

// ---------------------------------------------------------------
// GroupNorm + transpose: one block (1024 thr) per (batch, group).
// ---------------------------------------------------------------
__global__ void groupnorm_kernel(const float* __restrict__ x,
                                 const float* __restrict__ w,
                                 const float* __restrict__ b)
{
    const int bg = blockIdx.x;
    const int bb = bg / GRP;
    const int g  = bg % GRP;
    const int NE = CPG * NTOK;     // 65536
    const size_t base = ((size_t)bb * CCH + (size_t)g * CPG) * NTOK;
    const int t = threadIdx.x;

    float s = 0.f, ss = 0.f;
    for (int i = t * 4; i < NE; i += 4096) {
        float4 v = *reinterpret_cast<const float4*>(&x[base + i]);
        s  += v.x + v.y + v.z + v.w;
        ss += v.x * v.x + v.y * v.y + v.z * v.z + v.w * v.w;
    }
    __shared__ float sh[1024], sh2[1024];
    sh[t] = s; sh2[t] = ss;
    __syncthreads();
    for (int o = 512; o > 0; o >>= 1) {
        if (t < o) { sh[t] += sh[t + o]; sh2[t] += sh2[t + o]; }
        __syncthreads();
    }
    const float mu   = sh[0] / (float)NE;
    const float var  = sh2[0] / (float)NE - mu * mu;
    const float rstd = rsqrtf(var + EPSV);

    __shared__ float ts[16][65];
    const int c_l = t >> 6;
    const int n_l = t & 63;
    const int c   = g * CPG + c_l;
    const float sc = rstd * w[c];
    const float sb = b[c] - mu * sc;
    const int wn = t >> 4;
    const int wc = t & 15;
    __half* dst = g_hn + (size_t)bb * NTOK * CCH + g * CPG;

    for (int n0 = 0; n0 < NTOK; n0 += 64) {
        ts[c_l][n_l] = x[base + (size_t)c_l * NTOK + n0 + n_l] * sc + sb;
        __syncthreads();
        dst[(size_t)(n0 + wn) * CCH + wc] = __float2half_rn(ts[wc][wn]);
        __syncthreads();
    }
}

// ---------------------------------------------------------------
// Row softmax: fp16 in-place over g_p. One block per row.
// ---------------------------------------------------------------
__global__ void softmax_kernel()
{
    const size_t row = blockIdx.x;
    __half* p = g_p + row * (size_t)NTOK;
    const int t = threadIdx.x;

    float loc[16];
    float mx = -1e30f;
#pragma unroll
    for (int i = 0; i < 4; i++) {
        uint2 u = *reinterpret_cast<const uint2*>(&p[t * 4 + i * 1024]);
        __half2 h0, h1;
        memcpy(&h0, &u.x, 4); memcpy(&h1, &u.y, 4);
        float2 f0 = __half22float2(h0), f1 = __half22float2(h1);
        loc[4*i] = f0.x; loc[4*i+1] = f0.y; loc[4*i+2] = f1.x; loc[4*i+3] = f1.y;
        mx = fmaxf(mx, fmaxf(fmaxf(f0.x, f0.y), fmaxf(f1.x, f1.y)));
    }
    __shared__ float sh[256];
    sh[t] = mx; __syncthreads();
    for (int o = 128; o > 0; o >>= 1) {
        if (t < o) sh[t] = fmaxf(sh[t], sh[t + o]);
        __syncthreads();
    }
    mx = sh[0];
    __syncthreads();

    float sum = 0.f;
#pragma unroll
    for (int i = 0; i < 16; i++) {
        loc[i] = __expf(loc[i] - mx);
        sum += loc[i];
    }
    sh[t] = sum; __syncthreads();
    for (int o = 128; o > 0; o >>= 1) {
        if (t < o) sh[t] += sh[t + o];
        __syncthreads();
    }
    const float inv = 1.0f / sh[0];
#pragma unroll
    for (int i = 0; i < 4; i++) {
        __half2 h0 = __floats2half2_rn(loc[4*i] * inv,   loc[4*i+1] * inv);
        __half2 h1 = __floats2half2_rn(loc[4*i+2] * inv, loc[4*i+3] * inv);
        uint2 u = make_uint2(h2_bits(h0), h2_bits(h1));
        *reinterpret_cast<uint2*>(&p[t * 4 + i * 1024]) = u;
    }
}

// ---------------------------------------------------------------
// fp32-acc fp16 GEMM body: CTA 128x256x128, 2-stage double buffer,
// 8 warps (2m x 4n), warp 64x64, fragment double-buffer pipeline.
// EPI: 0 none | 1 (acc+bias[n])*scale | 2 acc+bias[m]+resid
// OUTT: 0 fp32 | 1 fp16 | 2 fp16 transposed C[n*M+m]
// ---------------------------------------------------------------
template<int EPI, int OUTT>
__device__ __forceinline__ void gemm_body(
    char* smem, const __half* __restrict__ A, const __half* __restrict__ B,
    void* __restrict__ Cv, int M, int Nn, int K, int m0, int n0,
    const float* __restrict__ bias, const float* __restrict__ resid, float scale)
{
    const uint32_t sbase = smem_u32(smem);
    const int tid = threadIdx.x, wid = tid >> 5, lane = tid & 31;
    const int wm = (wid & 1) * 64;
    const int wn = (wid >> 1) * 64;
    const int g = lane >> 2, tg = lane & 3;

    float acc[4][8][4] = {};

    auto stage = [&](int buf, int k0) {
        char* da = smem + buf * STAGE_BYTES;
        char* db = da + A_BYTES;
#pragma unroll
        for (int i = 0; i < 8; i++) {
            int cid = tid + i * 256;
            int r = cid >> 4, c = cid & 15;
            uint32_t off = (uint32_t)(r * 256 + c * 16) ^ (uint32_t)((r & 7) << 4);
            cp16(da + off, A + (size_t)(m0 + r) * K + k0 + c * 8);
        }
#pragma unroll
        for (int i = 0; i < 16; i++) {
            int cid = tid + i * 256;
            int r = cid >> 4, c = cid & 15;
            uint32_t off = (uint32_t)(r * 256 + c * 16) ^ (uint32_t)((r & 7) << 4);
            cp16(db + off, B + (size_t)(n0 + r) * K + k0 + c * 8);
        }
    };

    const int lrowA = lane & 15;
    const int coffA = lane >> 4;
    const int browB = ((lane >> 4) << 3) + (lane & 7);
    const int bcoB  = (lane >> 3) & 1;
    const uint32_t swz = (uint32_t)((lane & 7) << 4);

    const int KT = K / BK;
    stage(0, 0);  CP_COMMIT();

    for (int kt = 0; kt < KT; kt++) {
        if (kt + 1 < KT) stage((kt + 1) & 1, (kt + 1) * BK);
        CP_COMMIT();
        asm volatile("cp.async.wait_group 1;");
        __syncthreads();

        const uint32_t abase = sbase + (kt & 1) * STAGE_BYTES;
        const uint32_t bbase = abase + A_BYTES;

        uint32_t bf[2][8][2];
        uint32_t a[2][4];

        auto ldB = [&](int buf, int ks) {
#pragma unroll
            for (int jr = 0; jr < 4; jr++) {
                uint32_t addr = bbase + (uint32_t)((wn + browB + 16 * jr) * 256)
                              + (((uint32_t)((ks * 2 + bcoB) * 16)) ^ swz);
                LDSM4(bf[buf][2*jr][0], bf[buf][2*jr][1],
                      bf[buf][2*jr+1][0], bf[buf][2*jr+1][1], addr);
            }
        };
        auto ldA = [&](int buf, int ks, int i) {
            uint32_t addr = abase + (uint32_t)((wm + 16 * i + lrowA) * 256)
                          + (((uint32_t)((ks * 2 + coffA) * 16)) ^ swz);
            LDSM4(a[buf][0], a[buf][1], a[buf][2], a[buf][3], addr);
        };

        ldB(0, 0);
        ldA(0, 0, 0);

#pragma unroll
        for (int ks = 0; ks < 8; ks++) {
#pragma unroll
            for (int i = 0; i < 4; i++) {
                if (i < 3) {
                    ldA((i + 1) & 1, ks, i + 1);
                } else if (ks < 7) {
                    ldB((ks + 1) & 1, ks + 1);
                    ldA(0, ks + 1, 0);
                }
#pragma unroll
                for (int j = 0; j < 8; j++)
                    mma_f16(acc[i][j], a[i & 1], bf[ks & 1][j]);
            }
        }
        __syncthreads();
    }

    // ---------------- epilogue ----------------
    if (OUTT == 0) {
        float* C = (float*)Cv;
#pragma unroll
        for (int i = 0; i < 4; i++) {
            const int m = m0 + wm + 16 * i + g;
#pragma unroll
            for (int j = 0; j < 8; j++) {
                const int n = n0 + wn + 8 * j + 2 * tg;
                float v0 = acc[i][j][0], v1 = acc[i][j][1];
                float v2 = acc[i][j][2], v3 = acc[i][j][3];
                if (EPI == 1) {
                    v0 = (v0 + bias[n]) * scale; v1 = (v1 + bias[n+1]) * scale;
                    v2 = (v2 + bias[n]) * scale; v3 = (v3 + bias[n+1]) * scale;
                }
                if (EPI == 2) {
                    const float* r0 = resid + (size_t)m * Nn + n;
                    const float* r1 = resid + (size_t)(m + 8) * Nn + n;
                    v0 += bias[m] + r0[0];     v1 += bias[m] + r0[1];
                    v2 += bias[m + 8] + r1[0]; v3 += bias[m + 8] + r1[1];
                }
                *reinterpret_cast<float2*>(&C[(size_t)m * Nn + n])       = make_float2(v0, v1);
                *reinterpret_cast<float2*>(&C[(size_t)(m + 8) * Nn + n]) = make_float2(v2, v3);
            }
        }
    } else if (OUTT == 1) {
        __half* C = (__half*)Cv;
#pragma unroll
        for (int i = 0; i < 4; i++) {
            const int m = m0 + wm + 16 * i + g;
#pragma unroll
            for (int j = 0; j < 8; j++) {
                const int n = n0 + wn + 8 * j + 2 * tg;
                float v0 = acc[i][j][0], v1 = acc[i][j][1];
                float v2 = acc[i][j][2], v3 = acc[i][j][3];
                if (EPI == 1) {
                    v0 = (v0 + bias[n]) * scale; v1 = (v1 + bias[n+1]) * scale;
                    v2 = (v2 + bias[n]) * scale; v3 = (v3 + bias[n+1]) * scale;
                }
                *reinterpret_cast<__half2*>(&C[(size_t)m * Nn + n])       = __floats2half2_rn(v0, v1);
                *reinterpret_cast<__half2*>(&C[(size_t)(m + 8) * Nn + n]) = __floats2half2_rn(v2, v3);
            }
        }
    } else {
        __half* C = (__half*)Cv;
        __syncthreads();
        char* tp = smem + wid * 8192;
#pragma unroll
        for (int i = 0; i < 4; i++) {
#pragma unroll
            for (int j = 0; j < 8; j++) {
                const int nl = 8 * j + 2 * tg;
                const int nch = n0 + wn + nl;
                float v0 = acc[i][j][0], v1 = acc[i][j][1];
                float v2 = acc[i][j][2], v3 = acc[i][j][3];
                if (EPI == 1) {
                    v0 = (v0 + bias[nch]) * scale; v1 = (v1 + bias[nch+1]) * scale;
                    v2 = (v2 + bias[nch]) * scale; v3 = (v3 + bias[nch+1]) * scale;
                }
                const int ml0 = 16 * i + g, ml1 = ml0 + 8;
                auto put = [&](int nn, int mm, float vv) {
                    uint32_t o = (uint32_t)(nn * 128 + ((((mm >> 3) ^ (nn & 7)) << 4)) + (mm & 7) * 2);
                    *reinterpret_cast<__half*>(tp + o) = __float2half_rn(vv);
                };
                put(nl,     ml0, v0); put(nl + 1, ml0, v1);
                put(nl,     ml1, v2); put(nl + 1, ml1, v3);
            }
        }
        __syncwarp();
#pragma unroll
        for (int r = 0; r < 64; r++) {
            uint32_t o = (uint32_t)(r * 128 + (((lane >> 2) ^ (r & 7)) << 4) + (lane & 3) * 4);
            uint32_t v = *reinterpret_cast<uint32_t*>(tp + o);
            *reinterpret_cast<uint32_t*>(&C[(size_t)(n0 + wn + r) * M + m0 + wm + lane * 2]) = v;
        }
    }
}

// ---------------------------------------------------------------
template<int EPI, int OUTT>
__global__ void __launch_bounds__(256, 1)
hgemm(const __half* __restrict__ A, const __half* __restrict__ B,
      void* __restrict__ Cv, int M, int Nn, int K,
      size_t sA, size_t sB, size_t sCe,
      const float* __restrict__ bias,
      const float* __restrict__ resid, size_t sR, float scale)
{
    extern __shared__ __align__(1024) char smem[];
    const int bz = blockIdx.z;
    char* cptr = (OUTT == 0)
        ? (char*)((float*)Cv + (size_t)bz * sCe)
        : (char*)((__half*)Cv + (size_t)bz * sCe);
    gemm_body<EPI, OUTT>(smem, A + (size_t)bz * sA, B + (size_t)bz * sB,
                         cptr, M, Nn, K, blockIdx.y * BM, blockIdx.x * BN,
                         bias, resid ? resid + (size_t)bz * sR : nullptr, scale);
}

// Fused QKV: grid.x = 6 (proj*2 + half), grid.y = 32, grid.z = BATCH
// Q gets (acc+bias)*att_scale so the S GEMM needs no scaling.
__global__ void __launch_bounds__(256, 1)
qkv_gemm(const __half* __restrict__ hn,
         const float* __restrict__ bq, const float* __restrict__ bk,
         const float* __restrict__ bv,
         __half* __restrict__ q, __half* __restrict__ k, __half* __restrict__ v,
         float att_scale)
{
    extern __shared__ __align__(1024) char smem[];
    const int p    = blockIdx.x >> 1;
    const int half = blockIdx.x & 1;
    const int bb   = blockIdx.z;
    const size_t sTok = (size_t)NTOK * CCH;
    const size_t sChn = (size_t)CCH * NTOK;
    const __half* W  = g_w16 + (size_t)p * CCH * CCH;
    const float* bi  = (p == 0) ? bq : (p == 1) ? bk : bv;
    const __half* A  = hn + (size_t)bb * sTok;
    const int m0 = blockIdx.y * BM, n0 = half * BN;
    const float sc = (p == 0) ? att_scale : 1.0f;

    if (p < 2) {
        __half* C = ((p == 0) ? q : k) + (size_t)bb * sTok;
        gemm_body<1, 1>(smem, A, W, C, NTOK, CCH, CCH, m0, n0, bi, nullptr, sc);
    } else {
        __half* C = v + (size_t)bb * sChn;
        gemm_body<1, 2>(smem, A, W, C, NTOK, CCH, CCH, m0, n0, bi, nullptr, 1.0f);
    }
}

// ---------------------------------------------------------------
// fp16-accumulate GEMM (S and PV): CTA 128x128x64, 128 thr
// (4 warps, 2m x 2n), warp 64x64. 3-stage ring. 2 CTAs/SM.
//   C[m,n] = sum_k A[m,k]*B[n,k]   (raw fp16 store)
// A: [*, K] ld=K.  B: [*, K] ld=K.  C: ld = ldC.
// ---------------------------------------------------------------
__global__ void __launch_bounds__(128, 2)
f16acc_gemm(const __half* __restrict__ Ag, const __half* __restrict__ Bg,
            __half* __restrict__ Cg, int K, int ldC,
            size_t sA, size_t sB, size_t sC)
{
    extern __shared__ __align__(1024) char smem[];
    const uint32_t sbase = smem_u32(smem);
    const int tid = threadIdx.x, wid = tid >> 5, lane = tid & 31;
    const int bz = blockIdx.z;
    const __half* A = Ag + (size_t)bz * sA;
    const __half* B = Bg + (size_t)bz * sB;
    __half* C = Cg + (size_t)bz * sC;
    const int m0 = blockIdx.y * SBM, n0 = blockIdx.x * SBN;
    const int wm = (wid & 1) * 64;
    const int wn = (wid >> 1) * 64;
    const int g = lane >> 2, tg = lane & 3;

    uint32_t acc[4][8][2] = {};

    auto stage = [&](int buf, int k0) {
        char* da = smem + buf * SSTAGE;
        char* db = da + SA_BYTES;
#pragma unroll
        for (int i = 0; i < 8; i++) {
            int cid = tid + i * 128;
            int r = cid >> 3, c = cid & 7;
            uint32_t off = (uint32_t)(r * 128 + c * 16) ^ (uint32_t)((r & 7) << 4);
            cp16(da + off, A + (size_t)(m0 + r) * K + k0 + c * 8);
        }
#pragma unroll
        for (int i = 0; i < 8; i++) {
            int cid = tid + i * 128;
            int r = cid >> 3, c = cid & 7;
            uint32_t off = (uint32_t)(r * 128 + c * 16) ^ (uint32_t)((r & 7) << 4);
            cp16(db + off, B + (size_t)(n0 + r) * K + k0 + c * 8);
        }
    };

    const int lrowA = lane & 15;
    const int coffA = lane >> 4;
    const int browB = ((lane >> 4) << 3) + (lane & 7);
    const int bcoB  = (lane >> 3) & 1;
    const uint32_t swz = (uint32_t)((lane & 7) << 4);

    const int KT = K / SBK;
    stage(0, 0);    CP_COMMIT();
    stage(1, SBK);  CP_COMMIT();

    for (int kt = 0; kt < KT; kt++) {
        asm volatile("cp.async.wait_group 1;");
        __syncthreads();
        if (kt + 2 < KT) stage((kt + 2) % 3, (kt + 2) * SBK);
        CP_COMMIT();

        const uint32_t abase = sbase + (kt % 3) * SSTAGE;
        const uint32_t bbase = abase + SA_BYTES;

#pragma unroll
        for (int ks = 0; ks < 4; ks++) {
            uint32_t bf[8][2];
#pragma unroll
            for (int jr = 0; jr < 4; jr++) {
                uint32_t addr = bbase + (uint32_t)((wn + browB + 16 * jr) * 128)
                              + (((uint32_t)((ks * 2 + bcoB) * 16)) ^ swz);
                LDSM4(bf[2*jr][0], bf[2*jr][1], bf[2*jr+1][0], bf[2*jr+1][1], addr);
            }
#pragma unroll
            for (int i = 0; i < 4; i++) {
                uint32_t a[4];
                uint32_t addr = abase + (uint32_t)((wm + 16 * i + lrowA) * 128)
                              + (((uint32_t)((ks * 2 + coffA) * 16)) ^ swz);
                LDSM4(a[0], a[1], a[2], a[3], addr);
#pragma unroll
                for (int j = 0; j < 8; j++)
                    mma_f16a(acc[i][j], a, bf[j]);
            }
        }
        __syncthreads();
    }

#pragma unroll
    for (int i = 0; i < 4; i++) {
        const int m = m0 + wm + 16 * i + g;
#pragma unroll
        for (int j = 0; j < 8; j++) {
            const int n = n0 + wn + 8 * j + 2 * tg;
            *reinterpret_cast<uint32_t*>(&C[(size_t)m * ldC + n])       = acc[i][j][0];
            *reinterpret_cast<uint32_t*>(&C[(size_t)(m + 8) * ldC + n]) = acc[i][j][1];
        }
    }
}

// ---------------------------------------------------------------
extern "C" void kernel_launch(void* const* d_in, const int* in_sizes, int n_in,
                              void* d_out, int out_size)
{
    const float* x    = (const float*)d_in[0];
    const float* gn_w = (const float*)d_in[1];
    const float* gn_b = (const float*)d_in[2];
    const float* wq   = (const float*)d_in[3];
    const float* bq   = (const float*)d_in[4];
    const float* wk   = (const float*)d_in[5];
    const float* bk   = (const float*)d_in[6];
    const float* wv   = (const float*)d_in[7];
    const float* bv   = (const float*)d_in[8];
    const float* wo   = (const float*)d_in[9];
    const float* bo   = (const float*)d_in[10];
    float* out = (float*)d_out;

    __half *hn, *q, *k, *vt, *o, *p, *w16;
    cudaGetSymbolAddress((void**)&hn, g_hn);
    cudaGetSymbolAddress((void**)&q,  g_q);
    cudaGetSymbolAddress((void**)&k,  g_k);
    cudaGetSymbolAddress((void**)&vt, g_vt);
    cudaGetSymbolAddress((void**)&o,  g_o);
    cudaGetSymbolAddress((void**)&p,  g_p);
    cudaGetSymbolAddress((void**)&w16, g_w16);
    const __half* wo16 = w16 + 3 * (size_t)CCH * CCH;

    const size_t sTok = (size_t)NTOK * CCH;
    const size_t sChn = (size_t)CCH * NTOK;
    const size_t sAtt = (size_t)NTOK * NTOK;
    const float att_scale = 1.0f / sqrtf((float)CCH);

    cudaFuncSetAttribute(qkv_gemm,    cudaFuncAttributeMaxDynamicSharedMemorySize, DSMEM);
    cudaFuncSetAttribute(f16acc_gemm, cudaFuncAttributeMaxDynamicSharedMemorySize, DSMEM_S);
    cudaFuncSetAttribute(hgemm<2, 0>, cudaFuncAttributeMaxDynamicSharedMemorySize, DSMEM);

    // 0) weights -> fp16
    convw_kernel<<<dim3(CCH * CCH / 1024, 4), 256>>>(wq, wk, wv, wo);

    // 1) GroupNorm -> g_hn [b, n, c] fp16 (transposed)
    groupnorm_kernel<<<BATCH * GRP, 1024>>>(x, gn_w, gn_b);

    // 2) fused QKV (V transposed; Q pre-scaled by att_scale)
    qkv_gemm<<<dim3(6, NTOK / BM, BATCH), 256, DSMEM>>>(hn, bq, bk, bv, q, k, vt,
                                                        att_scale);

    // 3) S = Q K^T  -> g_p (fp16 accumulate)
    f16acc_gemm<<<dim3(NTOK / SBN, NTOK / SBM, BATCH), 128, DSMEM_S>>>(
        q, k, p, CCH, NTOK, sTok, sTok, sAtt);

    // 4) softmax in-place on g_p
    softmax_kernel<<<BATCH * NTOK, 256>>>();

    // 5) O = P V  (fp16 accumulate; A=P ld NTOK, B=V^T ld NTOK, C=O ld CCH)
    f16acc_gemm<<<dim3(CCH / SBN, NTOK / SBM, BATCH), 128, DSMEM_S>>>(
        p, vt, o, NTOK, CCH, sAtt, sChn, sTok);

    // 6) out[b,c,n] = x + bo[c] + wo @ O^T
    hgemm<2, 0><<<dim3(NTOK / BN, CCH / BM, BATCH), 256, DSMEM>>>(
        wo16, o, out, CCH, NTOK, CCH, 0, sTok, sChn, bo, x, sChn, 1.0f);
}

// round 15
// speedup vs baseline: 1.0235x; 1.0235x over previous
#include <cuda_runtime.h>
#include <cuda_fp16.h>
#include <math.h>
#include <stdint.h>

#define BATCH 2
#define CCH   512
#define NTOK  4096
#define GRP   32
#define CPG   (CCH / GRP)
#define EPSV  1e-6f

// fp32-acc GEMM tiling (QKV / proj)
#define BM 128
#define BN 256
#define BK 128
#define A_BYTES (BM * BK * 2)          // 32768
#define B_BYTES (BN * BK * 2)          // 65536
#define STAGE_BYTES (A_BYTES + B_BYTES)
#define DSMEM (2 * STAGE_BYTES)        // 196608

// fp16-acc GEMM tiling (S / PV): CTA 128x128x64, 4 warps, 2 CTAs/SM
#define SBM 128
#define SBN 128
#define SBK 64
#define SA_BYTES (SBM * SBK * 2)        // 16384
#define SB_BYTES (SBN * SBK * 2)        // 16384
#define SSTAGE (SA_BYTES + SB_BYTES)    // 32768
#define DSMEM_S (3 * SSTAGE)            // 98304

// -------- scratch (__device__ globals; no allocation allowed) --------
__device__ __half g_hn[(size_t)BATCH * NTOK * CCH];   // GN out, TRANSPOSED [b, n, c]
__device__ __half g_q [(size_t)BATCH * NTOK * CCH];   // [b, n, c]  (pre-scaled by att_scale)
__device__ __half g_k [(size_t)BATCH * NTOK * CCH];   // [b, n, c]
__device__ __half g_vt[(size_t)BATCH * CCH * NTOK];   // V TRANSPOSED [b, c, n]
__device__ __half g_o [(size_t)BATCH * NTOK * CCH];   // [b, n, c]
__device__ __half g_p [(size_t)BATCH * NTOK * NTOK];  // scores -> probs (fp16, in-place)
__device__ __half g_w16[4 * (size_t)CCH * CCH];       // wq, wk, wv, wo in fp16
__device__ float  g_gnstat[BATCH * GRP * 2];          // mu, rstd per (b, g)

// ---------------- helpers ----------------
__device__ __forceinline__ uint32_t smem_u32(const void* p) {
    uint32_t a;
    asm("{ .reg .u64 t; cvta.to.shared.u64 t, %1; cvt.u32.u64 %0, t; }"
        : "=r"(a) : "l"(p));
    return a;
}
__device__ __forceinline__ void cp16(void* dst, const void* src) {
    uint32_t d = smem_u32(dst);
    asm volatile("cp.async.cg.shared.global [%0], [%1], 16;" :: "r"(d), "l"(src));
}
#define CP_COMMIT() asm volatile("cp.async.commit_group;")

#define LDSM4(r0, r1, r2, r3, addr) \
    asm volatile("ldmatrix.sync.aligned.m8n8.x4.shared.b16 {%0,%1,%2,%3}, [%4];" \
        : "=r"(r0), "=r"(r1), "=r"(r2), "=r"(r3) : "r"(addr))

__device__ __forceinline__ void mma_f16(float* d, const uint32_t* a, const uint32_t* b) {
    asm volatile(
        "mma.sync.aligned.m16n8k16.row.col.f32.f16.f16.f32 "
        "{%0,%1,%2,%3},{%4,%5,%6,%7},{%8,%9},{%0,%1,%2,%3};"
        : "+f"(d[0]), "+f"(d[1]), "+f"(d[2]), "+f"(d[3])
        : "r"(a[0]), "r"(a[1]), "r"(a[2]), "r"(a[3]), "r"(b[0]), "r"(b[1]));
}

__device__ __forceinline__ void mma_f16a(uint32_t* d, const uint32_t* a, const uint32_t* b) {
    asm volatile(
        "mma.sync.aligned.m16n8k16.row.col.f16.f16.f16.f16 "
        "{%0,%1},{%2,%3,%4,%5},{%6,%7},{%0,%1};"
        : "+r"(d[0]), "+r"(d[1])
        : "r"(a[0]), "r"(a[1]), "r"(a[2]), "r"(a[3]), "r"(b[0]), "r"(b[1]));
}

__device__ __forceinline__ uint32_t h2_bits(__half2 h) {
    uint32_t u;
    memcpy(&u, &h, 4);
    return u;
}

// ---------------------------------------------------------------
// Weight conversion fp32 -> fp16
// ---------------------------------------------------------------
__global__ void convw_kernel(const float* __restrict__ a, const float* __restrict__ b,
                             const float* __restrict__ c, const float* __restrict__ d)
{
    const float* srcs[4] = {a, b, c, d};
    const float* src = srcs[blockIdx.y];
    __half* dst = g_w16 + (size_t)blockIdx.y * CCH * CCH;
    int i = (blockIdx.x * 256 + threadIdx.x) * 4;
    float4 v = *reinterpret_cast<const float4*>(&src[i]);
    *reinterpret_cast<__half2*>(&dst[i])     = __floats2half2_rn(v.x, v.y);
    *reinterpret_cast<__half2*>(&dst[i + 2]) = __floats2half2_rn(v.z, v.w);
}

// ---------------------------------------------------------------
// GN stats: one block (1024 thr) per (batch, group); writes mu, rstd
// ---------------------------------------------------------------
__global__ void gnstat_kernel(const float* __restrict__ x)
{
    const int bg = blockIdx.x;
    const int NE = CPG * NTOK;     // 65536
    const size_t base = (size_t)bg * NE;
    const int t = threadIdx.x;

    float s = 0.f, ss = 0.f;
    for (int i = t * 4; i < NE; i += 4096) {
        float4 v = *reinterpret_cast<const float4*>(&x[base + i]);
        s  += v.x + v.y + v.z + v.w;
        ss += v.x * v.x + v.y * v.y + v.z * v.z + v.w * v.w;
    }
    __shared__ float sh[1024], sh2[1024];
    sh[t] = s; sh2[t] = ss;
    __syncthreads();
    for (int o = 512; o > 0; o >>= 1) {
        if (t < o) { sh[t] += sh[t + o]; sh2[t] += sh2[t + o]; }
        __syncthreads();
    }
    if (t == 0) {
        const float mu  = sh[0] / (float)NE;
        const float var = sh2[0] / (float)NE - mu * mu;
        g_gnstat[bg * 2]     = mu;
        g_gnstat[bg * 2 + 1] = rsqrtf(var + EPSV);
    }
}

// ---------------------------------------------------------------
// GN apply + transpose: block handles 64c x 64n tile. 256 threads.
// grid: (NTOK/64, CCH/64, BATCH). Coalesced reads & packed writes.
// ---------------------------------------------------------------
__global__ void gnapply_kernel(const float* __restrict__ x,
                               const float* __restrict__ w,
                               const float* __restrict__ b)
{
    __shared__ float ts[64][65];
    __shared__ float ssc[64], ssb[64];
    const int n0 = blockIdx.x * 64;
    const int c0 = blockIdx.y * 64;
    const int bb = blockIdx.z;
    const int t = threadIdx.x;
    const size_t xbase = (size_t)bb * CCH * NTOK;

    if (t < 64) {
        const int c = c0 + t;
        const int bg = bb * GRP + c / CPG;
        const float mu   = g_gnstat[bg * 2];
        const float rstd = g_gnstat[bg * 2 + 1];
        const float sc = rstd * w[c];
        ssc[t] = sc;
        ssb[t] = b[c] - mu * sc;
    }
    __syncthreads();

    // load: 256 threads, 4 c-rows per pass, 16 passes; 64 floats/row
    {
        const int ci = t >> 6;      // 0..3
        const int nj = t & 63;
#pragma unroll
        for (int r = 0; r < 16; r++) {
            const int c = ci + r * 4;
            ts[c][nj] = x[xbase + (size_t)(c0 + c) * NTOK + n0 + nj];
        }
    }
    __syncthreads();

    // store: thread t -> n = t>>2 (64 rows), cpart = t&3 (16 ch = 32B)
    {
        const int n = t >> 2;
        const int cp = (t & 3) * 16;
        __half hv[16];
#pragma unroll
        for (int i = 0; i < 16; i++)
            hv[i] = __float2half_rn(ts[cp + i][n] * ssc[cp + i] + ssb[cp + i]);
        __half* dst = g_hn + (size_t)bb * NTOK * CCH + (size_t)(n0 + n) * CCH + c0 + cp;
        *reinterpret_cast<uint4*>(dst) = *reinterpret_cast<uint4*>(hv);
        *reinterpret_cast<uint4*>(dst + 8) = *reinterpret_cast<uint4*>(hv + 8);
    }
}

// ---------------------------------------------------------------
// Row softmax: fp16 in-place over g_p. One block per row.
// ---------------------------------------------------------------
__global__ void softmax_kernel()
{
    const size_t row = blockIdx.x;
    __half* p = g_p + row * (size_t)NTOK;
    const int t = threadIdx.x;

    float loc[16];
    float mx = -1e30f;
#pragma unroll
    for (int i = 0; i < 4; i++) {
        uint2 u = *reinterpret_cast<const uint2*>(&p[t * 4 + i * 1024]);
        __half2 h0, h1;
        memcpy(&h0, &u.x, 4); memcpy(&h1, &u.y, 4);
        float2 f0 = __half22float2(h0), f1 = __half22float2(h1);
        loc[4*i] = f0.x; loc[4*i+1] = f0.y; loc[4*i+2] = f1.x; loc[4*i+3] = f1.y;
        mx = fmaxf(mx, fmaxf(fmaxf(f0.x, f0.y), fmaxf(f1.x, f1.y)));
    }
    __shared__ float sh[256];
    sh[t] = mx; __syncthreads();
    for (int o = 128; o > 0; o >>= 1) {
        if (t < o) sh[t] = fmaxf(sh[t], sh[t + o]);
        __syncthreads();
    }
    mx = sh[0];
    __syncthreads();

    float sum = 0.f;
#pragma unroll
    for (int i = 0; i < 16; i++) {
        loc[i] = __expf(loc[i] - mx);
        sum += loc[i];
    }
    sh[t] = sum; __syncthreads();
    for (int o = 128; o > 0; o >>= 1) {
        if (t < o) sh[t] += sh[t + o];
        __syncthreads();
    }
    const float inv = 1.0f / sh[0];
#pragma unroll
    for (int i = 0; i < 4; i++) {
        __half2 h0 = __floats2half2_rn(loc[4*i] * inv,   loc[4*i+1] * inv);
        __half2 h1 = __floats2half2_rn(loc[4*i+2] * inv, loc[4*i+3] * inv);
        uint2 u = make_uint2(h2_bits(h0), h2_bits(h1));
        *reinterpret_cast<uint2*>(&p[t * 4 + i * 1024]) = u;
    }
}

// ---------------------------------------------------------------
// fp32-acc fp16 GEMM body (QKV / proj): CTA 128x256x128, 2-stage,
// 8 warps (2m x 4n), warp 64x64, fragment double-buffer pipeline.
// ---------------------------------------------------------------
template<int EPI, int OUTT>
__device__ __forceinline__ void gemm_body(
    char* smem, const __half* __restrict__ A, const __half* __restrict__ B,
    void* __restrict__ Cv, int M, int Nn, int K, int m0, int n0,
    const float* __restrict__ bias, const float* __restrict__ resid, float scale)
{
    const uint32_t sbase = smem_u32(smem);
    const int tid = threadIdx.x, wid = tid >> 5, lane = tid & 31;
    const int wm = (wid & 1) * 64;
    const int wn = (wid >> 1) * 64;
    const int g = lane >> 2, tg = lane & 3;

    float acc[4][8][4] = {};

    auto stage = [&](int buf, int k0) {
        char* da = smem + buf * STAGE_BYTES;
        char* db = da + A_BYTES;
#pragma unroll
        for (int i = 0; i < 8; i++) {
            int cid = tid + i * 256;
            int r = cid >> 4, c = cid & 15;
            uint32_t off = (uint32_t)(r * 256 + c * 16) ^ (uint32_t)((r & 7) << 4);
            cp16(da + off, A + (size_t)(m0 + r) * K + k0 + c * 8);
        }
#pragma unroll
        for (int i = 0; i < 16; i++) {
            int cid = tid + i * 256;
            int r = cid >> 4, c = cid & 15;
            uint32_t off = (uint32_t)(r * 256 + c * 16) ^ (uint32_t)((r & 7) << 4);
            cp16(db + off, B + (size_t)(n0 + r) * K + k0 + c * 8);
        }
    };

    const int lrowA = lane & 15;
    const int coffA = lane >> 4;
    const int browB = ((lane >> 4) << 3) + (lane & 7);
    const int bcoB  = (lane >> 3) & 1;
    const uint32_t swz = (uint32_t)((lane & 7) << 4);

    const int KT = K / BK;
    stage(0, 0);  CP_COMMIT();

    for (int kt = 0; kt < KT; kt++) {
        if (kt + 1 < KT) stage((kt + 1) & 1, (kt + 1) * BK);
        CP_COMMIT();
        asm volatile("cp.async.wait_group 1;");
        __syncthreads();

        const uint32_t abase = sbase + (kt & 1) * STAGE_BYTES;
        const uint32_t bbase = abase + A_BYTES;

        uint32_t bf[2][8][2];
        uint32_t a[2][4];

        auto ldB = [&](int buf, int ks) {
#pragma unroll
            for (int jr = 0; jr < 4; jr++) {
                uint32_t addr = bbase + (uint32_t)((wn + browB + 16 * jr) * 256)
                              + (((uint32_t)((ks * 2 + bcoB) * 16)) ^ swz);
                LDSM4(bf[buf][2*jr][0], bf[buf][2*jr][1],
                      bf[buf][2*jr+1][0], bf[buf][2*jr+1][1], addr);
            }
        };
        auto ldA = [&](int buf, int ks, int i) {
            uint32_t addr = abase + (uint32_t)((wm + 16 * i + lrowA) * 256)
                          + (((uint32_t)((ks * 2 + coffA) * 16)) ^ swz);
            LDSM4(a[buf][0], a[buf][1], a[buf][2], a[buf][3], addr);
        };

        ldB(0, 0);
        ldA(0, 0, 0);

#pragma unroll
        for (int ks = 0; ks < 8; ks++) {
#pragma unroll
            for (int i = 0; i < 4; i++) {
                if (i < 3) {
                    ldA((i + 1) & 1, ks, i + 1);
                } else if (ks < 7) {
                    ldB((ks + 1) & 1, ks + 1);
                    ldA(0, ks + 1, 0);
                }
#pragma unroll
                for (int j = 0; j < 8; j++)
                    mma_f16(acc[i][j], a[i & 1], bf[ks & 1][j]);
            }
        }
        __syncthreads();
    }

    // ---------------- epilogue ----------------
    if (OUTT == 0) {
        float* C = (float*)Cv;
#pragma unroll
        for (int i = 0; i < 4; i++) {
            const int m = m0 + wm + 16 * i + g;
#pragma unroll
            for (int j = 0; j < 8; j++) {
                const int n = n0 + wn + 8 * j + 2 * tg;
                float v0 = acc[i][j][0], v1 = acc[i][j][1];
                float v2 = acc[i][j][2], v3 = acc[i][j][3];
                if (EPI == 1) {
                    v0 = (v0 + bias[n]) * scale; v1 = (v1 + bias[n+1]) * scale;
                    v2 = (v2 + bias[n]) * scale; v3 = (v3 + bias[n+1]) * scale;
                }
                if (EPI == 2) {
                    const float* r0 = resid + (size_t)m * Nn + n;
                    const float* r1 = resid + (size_t)(m + 8) * Nn + n;
                    v0 += bias[m] + r0[0];     v1 += bias[m] + r0[1];
                    v2 += bias[m + 8] + r1[0]; v3 += bias[m + 8] + r1[1];
                }
                *reinterpret_cast<float2*>(&C[(size_t)m * Nn + n])       = make_float2(v0, v1);
                *reinterpret_cast<float2*>(&C[(size_t)(m + 8) * Nn + n]) = make_float2(v2, v3);
            }
        }
    } else if (OUTT == 1) {
        __half* C = (__half*)Cv;
#pragma unroll
        for (int i = 0; i < 4; i++) {
            const int m = m0 + wm + 16 * i + g;
#pragma unroll
            for (int j = 0; j < 8; j++) {
                const int n = n0 + wn + 8 * j + 2 * tg;
                float v0 = acc[i][j][0], v1 = acc[i][j][1];
                float v2 = acc[i][j][2], v3 = acc[i][j][3];
                if (EPI == 1) {
                    v0 = (v0 + bias[n]) * scale; v1 = (v1 + bias[n+1]) * scale;
                    v2 = (v2 + bias[n]) * scale; v3 = (v3 + bias[n+1]) * scale;
                }
                *reinterpret_cast<__half2*>(&C[(size_t)m * Nn + n])       = __floats2half2_rn(v0, v1);
                *reinterpret_cast<__half2*>(&C[(size_t)(m + 8) * Nn + n]) = __floats2half2_rn(v2, v3);
            }
        }
    } else {
        __half* C = (__half*)Cv;
        __syncthreads();
        char* tp = smem + wid * 8192;
#pragma unroll
        for (int i = 0; i < 4; i++) {
#pragma unroll
            for (int j = 0; j < 8; j++) {
                const int nl = 8 * j + 2 * tg;
                const int nch = n0 + wn + nl;
                float v0 = acc[i][j][0], v1 = acc[i][j][1];
                float v2 = acc[i][j][2], v3 = acc[i][j][3];
                if (EPI == 1) {
                    v0 = (v0 + bias[nch]) * scale; v1 = (v1 + bias[nch+1]) * scale;
                    v2 = (v2 + bias[nch]) * scale; v3 = (v3 + bias[nch+1]) * scale;
                }
                const int ml0 = 16 * i + g, ml1 = ml0 + 8;
                auto put = [&](int nn, int mm, float vv) {
                    uint32_t o = (uint32_t)(nn * 128 + ((((mm >> 3) ^ (nn & 7)) << 4)) + (mm & 7) * 2);
                    *reinterpret_cast<__half*>(tp + o) = __float2half_rn(vv);
                };
                put(nl,     ml0, v0); put(nl + 1, ml0, v1);
                put(nl,     ml1, v2); put(nl + 1, ml1, v3);
            }
        }
        __syncwarp();
#pragma unroll
        for (int r = 0; r < 64; r++) {
            uint32_t o = (uint32_t)(r * 128 + (((lane >> 2) ^ (r & 7)) << 4) + (lane & 3) * 4);
            uint32_t v = *reinterpret_cast<uint32_t*>(tp + o);
            *reinterpret_cast<uint32_t*>(&C[(size_t)(n0 + wn + r) * M + m0 + wm + lane * 2]) = v;
        }
    }
}

// ---------------------------------------------------------------
template<int EPI, int OUTT>
__global__ void __launch_bounds__(256, 1)
hgemm(const __half* __restrict__ A, const __half* __restrict__ B,
      void* __restrict__ Cv, int M, int Nn, int K,
      size_t sA, size_t sB, size_t sCe,
      const float* __restrict__ bias,
      const float* __restrict__ resid, size_t sR, float scale)
{
    extern __shared__ __align__(1024) char smem[];
    const int bz = blockIdx.z;
    char* cptr = (OUTT == 0)
        ? (char*)((float*)Cv + (size_t)bz * sCe)
        : (char*)((__half*)Cv + (size_t)bz * sCe);
    gemm_body<EPI, OUTT>(smem, A + (size_t)bz * sA, B + (size_t)bz * sB,
                         cptr, M, Nn, K, blockIdx.y * BM, blockIdx.x * BN,
                         bias, resid ? resid + (size_t)bz * sR : nullptr, scale);
}

// Fused QKV: grid.x = 6, grid.y = 32, grid.z = BATCH
__global__ void __launch_bounds__(256, 1)
qkv_gemm(const __half* __restrict__ hn,
         const float* __restrict__ bq, const float* __restrict__ bk,
         const float* __restrict__ bv,
         __half* __restrict__ q, __half* __restrict__ k, __half* __restrict__ v,
         float att_scale)
{
    extern __shared__ __align__(1024) char smem[];
    const int p    = blockIdx.x >> 1;
    const int half = blockIdx.x & 1;
    const int bb   = blockIdx.z;
    const size_t sTok = (size_t)NTOK * CCH;
    const size_t sChn = (size_t)CCH * NTOK;
    const __half* W  = g_w16 + (size_t)p * CCH * CCH;
    const float* bi  = (p == 0) ? bq : (p == 1) ? bk : bv;
    const __half* A  = hn + (size_t)bb * sTok;
    const int m0 = blockIdx.y * BM, n0 = half * BN;
    const float sc = (p == 0) ? att_scale : 1.0f;

    if (p < 2) {
        __half* C = ((p == 0) ? q : k) + (size_t)bb * sTok;
        gemm_body<1, 1>(smem, A, W, C, NTOK, CCH, CCH, m0, n0, bi, nullptr, sc);
    } else {
        __half* C = v + (size_t)bb * sChn;
        gemm_body<1, 2>(smem, A, W, C, NTOK, CCH, CCH, m0, n0, bi, nullptr, 1.0f);
    }
}

// ---------------------------------------------------------------
// fp16-accumulate GEMM (S / PV), compile-time K and LDC.
// CTA 128x128x64, 128 thr (4 warps, 2m x 2n), warp 64x64.
// 3-stage ring. 2 CTAs/SM.
// ---------------------------------------------------------------
template<int K, int LDC>
__global__ void __launch_bounds__(128, 2)
f16acc_gemm(const __half* __restrict__ Ag, const __half* __restrict__ Bg,
            __half* __restrict__ Cg, size_t sA, size_t sB, size_t sC)
{
    extern __shared__ __align__(1024) char smem[];
    const uint32_t sbase = smem_u32(smem);
    const int tid = threadIdx.x, wid = tid >> 5, lane = tid & 31;
    const int bz = blockIdx.z;
    const __half* A = Ag + (size_t)bz * sA;
    const __half* B = Bg + (size_t)bz * sB;
    __half* C = Cg + (size_t)bz * sC;
    const int m0 = blockIdx.y * SBM, n0 = blockIdx.x * SBN;
    const int wm = (wid & 1) * 64;
    const int wn = (wid >> 1) * 64;
    const int g = lane >> 2, tg = lane & 3;

    uint32_t acc[4][8][2] = {};

    auto stage = [&](int buf, int k0) {
        char* da = smem + buf * SSTAGE;
        char* db = da + SA_BYTES;
#pragma unroll
        for (int i = 0; i < 8; i++) {
            int cid = tid + i * 128;
            int r = cid >> 3, c = cid & 7;
            uint32_t off = (uint32_t)(r * 128 + c * 16) ^ (uint32_t)((r & 7) << 4);
            cp16(da + off, A + (size_t)(m0 + r) * K + k0 + c * 8);
        }
#pragma unroll
        for (int i = 0; i < 8; i++) {
            int cid = tid + i * 128;
            int r = cid >> 3, c = cid & 7;
            uint32_t off = (uint32_t)(r * 128 + c * 16) ^ (uint32_t)((r & 7) << 4);
            cp16(db + off, B + (size_t)(n0 + r) * K + k0 + c * 8);
        }
    };

    const int lrowA = lane & 15;
    const int coffA = lane >> 4;
    const int browB = ((lane >> 4) << 3) + (lane & 7);
    const int bcoB  = (lane >> 3) & 1;
    const uint32_t swz = (uint32_t)((lane & 7) << 4);

    constexpr int KT = K / SBK;
    stage(0, 0);    CP_COMMIT();
    stage(1, SBK);  CP_COMMIT();

#pragma unroll 1
    for (int kt = 0; kt < KT; kt++) {
        asm volatile("cp.async.wait_group 1;");
        __syncthreads();
        if (kt + 2 < KT) stage((kt + 2) % 3, (kt + 2) * SBK);
        CP_COMMIT();

        const uint32_t abase = sbase + (kt % 3) * SSTAGE;
        const uint32_t bbase = abase + SA_BYTES;

#pragma unroll
        for (int ks = 0; ks < 4; ks++) {
            uint32_t bf[8][2];
#pragma unroll
            for (int jr = 0; jr < 4; jr++) {
                uint32_t addr = bbase + (uint32_t)((wn + browB + 16 * jr) * 128)
                              + (((uint32_t)((ks * 2 + bcoB) * 16)) ^ swz);
                LDSM4(bf[2*jr][0], bf[2*jr][1], bf[2*jr+1][0], bf[2*jr+1][1], addr);
            }
#pragma unroll
            for (int i = 0; i < 4; i++) {
                uint32_t a[4];
                uint32_t addr = abase + (uint32_t)((wm + 16 * i + lrowA) * 128)
                              + (((uint32_t)((ks * 2 + coffA) * 16)) ^ swz);
                LDSM4(a[0], a[1], a[2], a[3], addr);
#pragma unroll
                for (int j = 0; j < 8; j++)
                    mma_f16a(acc[i][j], a, bf[j]);
            }
        }
        __syncthreads();
    }

#pragma unroll
    for (int i = 0; i < 4; i++) {
        const int m = m0 + wm + 16 * i + g;
#pragma unroll
        for (int j = 0; j < 8; j++) {
            const int n = n0 + wn + 8 * j + 2 * tg;
            *reinterpret_cast<uint32_t*>(&C[(size_t)m * LDC + n])       = acc[i][j][0];
            *reinterpret_cast<uint32_t*>(&C[(size_t)(m + 8) * LDC + n]) = acc[i][j][1];
        }
    }
}

// ---------------------------------------------------------------
extern "C" void kernel_launch(void* const* d_in, const int* in_sizes, int n_in,
                              void* d_out, int out_size)
{
    const float* x    = (const float*)d_in[0];
    const float* gn_w = (const float*)d_in[1];
    const float* gn_b = (const float*)d_in[2];
    const float* wq   = (const float*)d_in[3];
    const float* bq   = (const float*)d_in[4];
    const float* wk   = (const float*)d_in[5];
    const float* bk   = (const float*)d_in[6];
    const float* wv   = (const float*)d_in[7];
    const float* bv   = (const float*)d_in[8];
    const float* wo   = (const float*)d_in[9];
    const float* bo   = (const float*)d_in[10];
    float* out = (float*)d_out;

    __half *hn, *q, *k, *vt, *o, *p, *w16;
    cudaGetSymbolAddress((void**)&hn, g_hn);
    cudaGetSymbolAddress((void**)&q,  g_q);
    cudaGetSymbolAddress((void**)&k,  g_k);
    cudaGetSymbolAddress((void**)&vt, g_vt);
    cudaGetSymbolAddress((void**)&o,  g_o);
    cudaGetSymbolAddress((void**)&p,  g_p);
    cudaGetSymbolAddress((void**)&w16, g_w16);
    const __half* wo16 = w16 + 3 * (size_t)CCH * CCH;

    const size_t sTok = (size_t)NTOK * CCH;
    const size_t sChn = (size_t)CCH * NTOK;
    const size_t sAtt = (size_t)NTOK * NTOK;
    const float att_scale = 1.0f / sqrtf((float)CCH);

    cudaFuncSetAttribute(qkv_gemm, cudaFuncAttributeMaxDynamicSharedMemorySize, DSMEM);
    cudaFuncSetAttribute(f16acc_gemm<CCH, NTOK>,  cudaFuncAttributeMaxDynamicSharedMemorySize, DSMEM_S);
    cudaFuncSetAttribute(f16acc_gemm<NTOK, CCH>,  cudaFuncAttributeMaxDynamicSharedMemorySize, DSMEM_S);
    cudaFuncSetAttribute(hgemm<2, 0>, cudaFuncAttributeMaxDynamicSharedMemorySize, DSMEM);

    // 0) weights -> fp16
    convw_kernel<<<dim3(CCH * CCH / 1024, 4), 256>>>(wq, wk, wv, wo);

    // 1) GroupNorm stats + apply/transpose -> g_hn [b, n, c] fp16
    gnstat_kernel<<<BATCH * GRP, 1024>>>(x);
    gnapply_kernel<<<dim3(NTOK / 64, CCH / 64, BATCH), 256>>>(x, gn_w, gn_b);

    // 2) fused QKV (V transposed; Q pre-scaled by att_scale)
    qkv_gemm<<<dim3(6, NTOK / BM, BATCH), 256, DSMEM>>>(hn, bq, bk, bv, q, k, vt,
                                                        att_scale);

    // 3) S = Q K^T  -> g_p (fp16 accumulate)
    f16acc_gemm<CCH, NTOK><<<dim3(NTOK / SBN, NTOK / SBM, BATCH), 128, DSMEM_S>>>(
        q, k, p, sTok, sTok, sAtt);

    // 4) softmax in-place on g_p
    softmax_kernel<<<BATCH * NTOK, 256>>>();

    // 5) O = P V  (fp16 accumulate)
    f16acc_gemm<NTOK, CCH><<<dim3(CCH / SBN, NTOK / SBM, BATCH), 128, DSMEM_S>>>(
        p, vt, o, sAtt, sChn, sTok);

    // 6) out[b,c,n] = x + bo[c] + wo @ O^T
    hgemm<2, 0><<<dim3(NTOK / BN, CCH / BM, BATCH), 256, DSMEM>>>(
        wo16, o, out, CCH, NTOK, CCH, 0, sTok, sChn, bo, x, sChn, 1.0f);
}

// round 16
// speedup vs baseline: 1.0461x; 1.0220x over previous
#include <cuda_runtime.h>
#include <cuda_fp16.h>
#include <math.h>
#include <stdint.h>

#define BATCH 2
#define CCH   512
#define NTOK  4096
#define GRP   32
#define CPG   (CCH / GRP)
#define EPSV  1e-6f
#define EXPOFF 5.0f

// fp32-acc GEMM tiling (QKV / proj)
#define BM 128
#define BN 256
#define BK 128
#define A_BYTES (BM * BK * 2)
#define B_BYTES (BN * BK * 2)
#define STAGE_BYTES (A_BYTES + B_BYTES)
#define DSMEM (2 * STAGE_BYTES)        // 196608

// fp16-acc GEMM tiling (S / PV): CTA 128x128x64, 4 warps, 2 CTAs/SM
#define SBM 128
#define SBN 128
#define SBK 64
#define SA_BYTES (SBM * SBK * 2)
#define SB_BYTES (SBN * SBK * 2)
#define SSTAGE (SA_BYTES + SB_BYTES)
#define DSMEM_S (3 * SSTAGE)            // 98304

// -------- scratch (__device__ globals; no allocation allowed) --------
__device__ __half g_hn[(size_t)BATCH * NTOK * CCH];   // GN out, TRANSPOSED [b, n, c]
__device__ __half g_q [(size_t)BATCH * NTOK * CCH];   // pre-scaled by att_scale
__device__ __half g_k [(size_t)BATCH * NTOK * CCH];
__device__ __half g_vt[(size_t)BATCH * CCH * NTOK];   // V TRANSPOSED [b, c, n]
__device__ __half g_o [(size_t)BATCH * NTOK * CCH];
__device__ __half g_p [(size_t)BATCH * NTOK * NTOK];  // exp(S-5) (fp16)
__device__ __half g_w16[4 * (size_t)CCH * CCH];
__device__ float  g_gnstat[BATCH * GRP * 2];          // mu, rstd per (b, g)
__device__ float  g_rinv[(size_t)BATCH * NTOK];       // 1 / rowsum

// ---------------- helpers ----------------
__device__ __forceinline__ uint32_t smem_u32(const void* p) {
    uint32_t a;
    asm("{ .reg .u64 t; cvta.to.shared.u64 t, %1; cvt.u32.u64 %0, t; }"
        : "=r"(a) : "l"(p));
    return a;
}
__device__ __forceinline__ void cp16(void* dst, const void* src) {
    uint32_t d = smem_u32(dst);
    asm volatile("cp.async.cg.shared.global [%0], [%1], 16;" :: "r"(d), "l"(src));
}
#define CP_COMMIT() asm volatile("cp.async.commit_group;")

#define LDSM4(r0, r1, r2, r3, addr) \
    asm volatile("ldmatrix.sync.aligned.m8n8.x4.shared.b16 {%0,%1,%2,%3}, [%4];" \
        : "=r"(r0), "=r"(r1), "=r"(r2), "=r"(r3) : "r"(addr))

__device__ __forceinline__ void mma_f16(float* d, const uint32_t* a, const uint32_t* b) {
    asm volatile(
        "mma.sync.aligned.m16n8k16.row.col.f32.f16.f16.f32 "
        "{%0,%1,%2,%3},{%4,%5,%6,%7},{%8,%9},{%0,%1,%2,%3};"
        : "+f"(d[0]), "+f"(d[1]), "+f"(d[2]), "+f"(d[3])
        : "r"(a[0]), "r"(a[1]), "r"(a[2]), "r"(a[3]), "r"(b[0]), "r"(b[1]));
}

__device__ __forceinline__ void mma_f16a(uint32_t* d, const uint32_t* a, const uint32_t* b) {
    asm volatile(
        "mma.sync.aligned.m16n8k16.row.col.f16.f16.f16.f16 "
        "{%0,%1},{%2,%3,%4,%5},{%6,%7},{%0,%1};"
        : "+r"(d[0]), "+r"(d[1])
        : "r"(a[0]), "r"(a[1]), "r"(a[2]), "r"(a[3]), "r"(b[0]), "r"(b[1]));
}

__device__ __forceinline__ uint32_t h2_bits(__half2 h) {
    uint32_t u;
    memcpy(&u, &h, 4);
    return u;
}
__device__ __forceinline__ __half2 bits_h2(uint32_t u) {
    __half2 h;
    memcpy(&h, &u, 4);
    return h;
}

// ---------------------------------------------------------------
__global__ void convw_kernel(const float* __restrict__ a, const float* __restrict__ b,
                             const float* __restrict__ c, const float* __restrict__ d)
{
    const float* srcs[4] = {a, b, c, d};
    const float* src = srcs[blockIdx.y];
    __half* dst = g_w16 + (size_t)blockIdx.y * CCH * CCH;
    int i = (blockIdx.x * 256 + threadIdx.x) * 4;
    float4 v = *reinterpret_cast<const float4*>(&src[i]);
    *reinterpret_cast<__half2*>(&dst[i])     = __floats2half2_rn(v.x, v.y);
    *reinterpret_cast<__half2*>(&dst[i + 2]) = __floats2half2_rn(v.z, v.w);
}

// ---------------------------------------------------------------
__global__ void gnstat_kernel(const float* __restrict__ x)
{
    const int bg = blockIdx.x;
    const int NE = CPG * NTOK;
    const size_t base = (size_t)bg * NE;
    const int t = threadIdx.x;

    float s = 0.f, ss = 0.f;
    for (int i = t * 4; i < NE; i += 4096) {
        float4 v = *reinterpret_cast<const float4*>(&x[base + i]);
        s  += v.x + v.y + v.z + v.w;
        ss += v.x * v.x + v.y * v.y + v.z * v.z + v.w * v.w;
    }
    __shared__ float sh[1024], sh2[1024];
    sh[t] = s; sh2[t] = ss;
    __syncthreads();
    for (int o = 512; o > 0; o >>= 1) {
        if (t < o) { sh[t] += sh[t + o]; sh2[t] += sh2[t + o]; }
        __syncthreads();
    }
    if (t == 0) {
        const float mu  = sh[0] / (float)NE;
        const float var = sh2[0] / (float)NE - mu * mu;
        g_gnstat[bg * 2]     = mu;
        g_gnstat[bg * 2 + 1] = rsqrtf(var + EPSV);
    }
}

// ---------------------------------------------------------------
__global__ void gnapply_kernel(const float* __restrict__ x,
                               const float* __restrict__ w,
                               const float* __restrict__ b)
{
    __shared__ float ts[64][65];
    __shared__ float ssc[64], ssb[64];
    const int n0 = blockIdx.x * 64;
    const int c0 = blockIdx.y * 64;
    const int bb = blockIdx.z;
    const int t = threadIdx.x;
    const size_t xbase = (size_t)bb * CCH * NTOK;

    if (t < 64) {
        const int c = c0 + t;
        const int bg = bb * GRP + c / CPG;
        const float mu   = g_gnstat[bg * 2];
        const float rstd = g_gnstat[bg * 2 + 1];
        const float sc = rstd * w[c];
        ssc[t] = sc;
        ssb[t] = b[c] - mu * sc;
    }
    __syncthreads();

    {
        const int ci = t >> 6;
        const int nj = t & 63;
#pragma unroll
        for (int r = 0; r < 16; r++) {
            const int c = ci + r * 4;
            ts[c][nj] = x[xbase + (size_t)(c0 + c) * NTOK + n0 + nj];
        }
    }
    __syncthreads();

    {
        const int n = t >> 2;
        const int cp = (t & 3) * 16;
        __half hv[16];
#pragma unroll
        for (int i = 0; i < 16; i++)
            hv[i] = __float2half_rn(ts[cp + i][n] * ssc[cp + i] + ssb[cp + i]);
        __half* dst = g_hn + (size_t)bb * NTOK * CCH + (size_t)(n0 + n) * CCH + c0 + cp;
        *reinterpret_cast<uint4*>(dst) = *reinterpret_cast<uint4*>(hv);
        *reinterpret_cast<uint4*>(dst + 8) = *reinterpret_cast<uint4*>(hv + 8);
    }
}

// ---------------------------------------------------------------
// Row sum of exp-scores: one block (256 thr) per row; writes 1/sum.
// ---------------------------------------------------------------
__global__ void rowsum_kernel()
{
    const size_t row = blockIdx.x;
    const __half* p = g_p + row * (size_t)NTOK;
    const int t = threadIdx.x;

    float s = 0.f;
#pragma unroll
    for (int i = 0; i < 2; i++) {
        uint4 u = *reinterpret_cast<const uint4*>(&p[t * 8 + i * 2048]);
        float2 f0 = __half22float2(bits_h2(u.x));
        float2 f1 = __half22float2(bits_h2(u.y));
        float2 f2 = __half22float2(bits_h2(u.z));
        float2 f3 = __half22float2(bits_h2(u.w));
        s += (f0.x + f0.y) + (f1.x + f1.y) + (f2.x + f2.y) + (f3.x + f3.y);
    }
    __shared__ float sh[256];
    sh[t] = s; __syncthreads();
    for (int o = 128; o > 0; o >>= 1) {
        if (t < o) sh[t] += sh[t + o];
        __syncthreads();
    }
    if (t == 0) g_rinv[row] = 1.0f / sh[0];
}

// ---------------------------------------------------------------
// fp32-acc fp16 GEMM body (QKV / proj): CTA 128x256x128, 2-stage,
// 8 warps (2m x 4n), warp 64x64, fragment double-buffer pipeline.
// ---------------------------------------------------------------
template<int EPI, int OUTT>
__device__ __forceinline__ void gemm_body(
    char* smem, const __half* __restrict__ A, const __half* __restrict__ B,
    void* __restrict__ Cv, int M, int Nn, int K, int m0, int n0,
    const float* __restrict__ bias, const float* __restrict__ resid, float scale)
{
    const uint32_t sbase = smem_u32(smem);
    const int tid = threadIdx.x, wid = tid >> 5, lane = tid & 31;
    const int wm = (wid & 1) * 64;
    const int wn = (wid >> 1) * 64;
    const int g = lane >> 2, tg = lane & 3;

    float acc[4][8][4] = {};

    auto stage = [&](int buf, int k0) {
        char* da = smem + buf * STAGE_BYTES;
        char* db = da + A_BYTES;
#pragma unroll
        for (int i = 0; i < 8; i++) {
            int cid = tid + i * 256;
            int r = cid >> 4, c = cid & 15;
            uint32_t off = (uint32_t)(r * 256 + c * 16) ^ (uint32_t)((r & 7) << 4);
            cp16(da + off, A + (size_t)(m0 + r) * K + k0 + c * 8);
        }
#pragma unroll
        for (int i = 0; i < 16; i++) {
            int cid = tid + i * 256;
            int r = cid >> 4, c = cid & 15;
            uint32_t off = (uint32_t)(r * 256 + c * 16) ^ (uint32_t)((r & 7) << 4);
            cp16(db + off, B + (size_t)(n0 + r) * K + k0 + c * 8);
        }
    };

    const int lrowA = lane & 15;
    const int coffA = lane >> 4;
    const int browB = ((lane >> 4) << 3) + (lane & 7);
    const int bcoB  = (lane >> 3) & 1;
    const uint32_t swz = (uint32_t)((lane & 7) << 4);

    const int KT = K / BK;
    stage(0, 0);  CP_COMMIT();

    for (int kt = 0; kt < KT; kt++) {
        if (kt + 1 < KT) stage((kt + 1) & 1, (kt + 1) * BK);
        CP_COMMIT();
        asm volatile("cp.async.wait_group 1;");
        __syncthreads();

        const uint32_t abase = sbase + (kt & 1) * STAGE_BYTES;
        const uint32_t bbase = abase + A_BYTES;

        uint32_t bf[2][8][2];
        uint32_t a[2][4];

        auto ldB = [&](int buf, int ks) {
#pragma unroll
            for (int jr = 0; jr < 4; jr++) {
                uint32_t addr = bbase + (uint32_t)((wn + browB + 16 * jr) * 256)
                              + (((uint32_t)((ks * 2 + bcoB) * 16)) ^ swz);
                LDSM4(bf[buf][2*jr][0], bf[buf][2*jr][1],
                      bf[buf][2*jr+1][0], bf[buf][2*jr+1][1], addr);
            }
        };
        auto ldA = [&](int buf, int ks, int i) {
            uint32_t addr = abase + (uint32_t)((wm + 16 * i + lrowA) * 256)
                          + (((uint32_t)((ks * 2 + coffA) * 16)) ^ swz);
            LDSM4(a[buf][0], a[buf][1], a[buf][2], a[buf][3], addr);
        };

        ldB(0, 0);
        ldA(0, 0, 0);

#pragma unroll
        for (int ks = 0; ks < 8; ks++) {
#pragma unroll
            for (int i = 0; i < 4; i++) {
                if (i < 3) {
                    ldA((i + 1) & 1, ks, i + 1);
                } else if (ks < 7) {
                    ldB((ks + 1) & 1, ks + 1);
                    ldA(0, ks + 1, 0);
                }
#pragma unroll
                for (int j = 0; j < 8; j++)
                    mma_f16(acc[i][j], a[i & 1], bf[ks & 1][j]);
            }
        }
        __syncthreads();
    }

    // ---------------- epilogue ----------------
    if (OUTT == 0) {
        float* C = (float*)Cv;
#pragma unroll
        for (int i = 0; i < 4; i++) {
            const int m = m0 + wm + 16 * i + g;
#pragma unroll
            for (int j = 0; j < 8; j++) {
                const int n = n0 + wn + 8 * j + 2 * tg;
                float v0 = acc[i][j][0], v1 = acc[i][j][1];
                float v2 = acc[i][j][2], v3 = acc[i][j][3];
                if (EPI == 1) {
                    v0 = (v0 + bias[n]) * scale; v1 = (v1 + bias[n+1]) * scale;
                    v2 = (v2 + bias[n]) * scale; v3 = (v3 + bias[n+1]) * scale;
                }
                if (EPI == 2) {
                    const float* r0 = resid + (size_t)m * Nn + n;
                    const float* r1 = resid + (size_t)(m + 8) * Nn + n;
                    v0 += bias[m] + r0[0];     v1 += bias[m] + r0[1];
                    v2 += bias[m + 8] + r1[0]; v3 += bias[m + 8] + r1[1];
                }
                *reinterpret_cast<float2*>(&C[(size_t)m * Nn + n])       = make_float2(v0, v1);
                *reinterpret_cast<float2*>(&C[(size_t)(m + 8) * Nn + n]) = make_float2(v2, v3);
            }
        }
    } else if (OUTT == 1) {
        __half* C = (__half*)Cv;
#pragma unroll
        for (int i = 0; i < 4; i++) {
            const int m = m0 + wm + 16 * i + g;
#pragma unroll
            for (int j = 0; j < 8; j++) {
                const int n = n0 + wn + 8 * j + 2 * tg;
                float v0 = acc[i][j][0], v1 = acc[i][j][1];
                float v2 = acc[i][j][2], v3 = acc[i][j][3];
                if (EPI == 1) {
                    v0 = (v0 + bias[n]) * scale; v1 = (v1 + bias[n+1]) * scale;
                    v2 = (v2 + bias[n]) * scale; v3 = (v3 + bias[n+1]) * scale;
                }
                *reinterpret_cast<__half2*>(&C[(size_t)m * Nn + n])       = __floats2half2_rn(v0, v1);
                *reinterpret_cast<__half2*>(&C[(size_t)(m + 8) * Nn + n]) = __floats2half2_rn(v2, v3);
            }
        }
    } else {
        __half* C = (__half*)Cv;
        __syncthreads();
        char* tp = smem + wid * 8192;
#pragma unroll
        for (int i = 0; i < 4; i++) {
#pragma unroll
            for (int j = 0; j < 8; j++) {
                const int nl = 8 * j + 2 * tg;
                const int nch = n0 + wn + nl;
                float v0 = acc[i][j][0], v1 = acc[i][j][1];
                float v2 = acc[i][j][2], v3 = acc[i][j][3];
                if (EPI == 1) {
                    v0 = (v0 + bias[nch]) * scale; v1 = (v1 + bias[nch+1]) * scale;
                    v2 = (v2 + bias[nch]) * scale; v3 = (v3 + bias[nch+1]) * scale;
                }
                const int ml0 = 16 * i + g, ml1 = ml0 + 8;
                auto put = [&](int nn, int mm, float vv) {
                    uint32_t o = (uint32_t)(nn * 128 + ((((mm >> 3) ^ (nn & 7)) << 4)) + (mm & 7) * 2);
                    *reinterpret_cast<__half*>(tp + o) = __float2half_rn(vv);
                };
                put(nl,     ml0, v0); put(nl + 1, ml0, v1);
                put(nl,     ml1, v2); put(nl + 1, ml1, v3);
            }
        }
        __syncwarp();
#pragma unroll
        for (int r = 0; r < 64; r++) {
            uint32_t o = (uint32_t)(r * 128 + (((lane >> 2) ^ (r & 7)) << 4) + (lane & 3) * 4);
            uint32_t v = *reinterpret_cast<uint32_t*>(tp + o);
            *reinterpret_cast<uint32_t*>(&C[(size_t)(n0 + wn + r) * M + m0 + wm + lane * 2]) = v;
        }
    }
}

// ---------------------------------------------------------------
template<int EPI, int OUTT>
__global__ void __launch_bounds__(256, 1)
hgemm(const __half* __restrict__ A, const __half* __restrict__ B,
      void* __restrict__ Cv, int M, int Nn, int K,
      size_t sA, size_t sB, size_t sCe,
      const float* __restrict__ bias,
      const float* __restrict__ resid, size_t sR, float scale)
{
    extern __shared__ __align__(1024) char smem[];
    const int bz = blockIdx.z;
    char* cptr = (OUTT == 0)
        ? (char*)((float*)Cv + (size_t)bz * sCe)
        : (char*)((__half*)Cv + (size_t)bz * sCe);
    gemm_body<EPI, OUTT>(smem, A + (size_t)bz * sA, B + (size_t)bz * sB,
                         cptr, M, Nn, K, blockIdx.y * BM, blockIdx.x * BN,
                         bias, resid ? resid + (size_t)bz * sR : nullptr, scale);
}

__global__ void __launch_bounds__(256, 1)
qkv_gemm(const __half* __restrict__ hn,
         const float* __restrict__ bq, const float* __restrict__ bk,
         const float* __restrict__ bv,
         __half* __restrict__ q, __half* __restrict__ k, __half* __restrict__ v,
         float att_scale)
{
    extern __shared__ __align__(1024) char smem[];
    const int p    = blockIdx.x >> 1;
    const int half = blockIdx.x & 1;
    const int bb   = blockIdx.z;
    const size_t sTok = (size_t)NTOK * CCH;
    const size_t sChn = (size_t)CCH * NTOK;
    const __half* W  = g_w16 + (size_t)p * CCH * CCH;
    const float* bi  = (p == 0) ? bq : (p == 1) ? bk : bv;
    const __half* A  = hn + (size_t)bb * sTok;
    const int m0 = blockIdx.y * BM, n0 = half * BN;
    const float sc = (p == 0) ? att_scale : 1.0f;

    if (p < 2) {
        __half* C = ((p == 0) ? q : k) + (size_t)bb * sTok;
        gemm_body<1, 1>(smem, A, W, C, NTOK, CCH, CCH, m0, n0, bi, nullptr, sc);
    } else {
        __half* C = v + (size_t)bb * sChn;
        gemm_body<1, 2>(smem, A, W, C, NTOK, CCH, CCH, m0, n0, bi, nullptr, 1.0f);
    }
}

// ---------------------------------------------------------------
// fp16-accumulate GEMM (S / PV), compile-time K and LDC.
// MODE 0: store raw fp16.  MODE 1: store exp(acc - EXPOFF) (S).
// MODE 2: store acc * g_rinv[batch*M + m]  (PV normalization).
// CTA 128x128x64, 128 thr (4 warps, 2m x 2n), warp 64x64.
// ---------------------------------------------------------------
template<int K, int LDC, int MODE>
__global__ void __launch_bounds__(128, 2)
f16acc_gemm(const __half* __restrict__ Ag, const __half* __restrict__ Bg,
            __half* __restrict__ Cg, size_t sA, size_t sB, size_t sC)
{
    extern __shared__ __align__(1024) char smem[];
    const uint32_t sbase = smem_u32(smem);
    const int tid = threadIdx.x, wid = tid >> 5, lane = tid & 31;
    const int bz = blockIdx.z;
    const __half* A = Ag + (size_t)bz * sA;
    const __half* B = Bg + (size_t)bz * sB;
    __half* C = Cg + (size_t)bz * sC;
    const int m0 = blockIdx.y * SBM, n0 = blockIdx.x * SBN;
    const int wm = (wid & 1) * 64;
    const int wn = (wid >> 1) * 64;
    const int g = lane >> 2, tg = lane & 3;

    uint32_t acc[4][8][2] = {};

    auto stage = [&](int buf, int k0) {
        char* da = smem + buf * SSTAGE;
        char* db = da + SA_BYTES;
#pragma unroll
        for (int i = 0; i < 8; i++) {
            int cid = tid + i * 128;
            int r = cid >> 3, c = cid & 7;
            uint32_t off = (uint32_t)(r * 128 + c * 16) ^ (uint32_t)((r & 7) << 4);
            cp16(da + off, A + (size_t)(m0 + r) * K + k0 + c * 8);
        }
#pragma unroll
        for (int i = 0; i < 8; i++) {
            int cid = tid + i * 128;
            int r = cid >> 3, c = cid & 7;
            uint32_t off = (uint32_t)(r * 128 + c * 16) ^ (uint32_t)((r & 7) << 4);
            cp16(db + off, B + (size_t)(n0 + r) * K + k0 + c * 8);
        }
    };

    const int lrowA = lane & 15;
    const int coffA = lane >> 4;
    const int browB = ((lane >> 4) << 3) + (lane & 7);
    const int bcoB  = (lane >> 3) & 1;
    const uint32_t swz = (uint32_t)((lane & 7) << 4);

    constexpr int KT = K / SBK;
    stage(0, 0);    CP_COMMIT();
    stage(1, SBK);  CP_COMMIT();

#pragma unroll 1
    for (int kt = 0; kt < KT; kt++) {
        asm volatile("cp.async.wait_group 1;");
        __syncthreads();
        if (kt + 2 < KT) stage((kt + 2) % 3, (kt + 2) * SBK);
        CP_COMMIT();

        const uint32_t abase = sbase + (kt % 3) * SSTAGE;
        const uint32_t bbase = abase + SA_BYTES;

#pragma unroll
        for (int ks = 0; ks < 4; ks++) {
            uint32_t bf[8][2];
#pragma unroll
            for (int jr = 0; jr < 4; jr++) {
                uint32_t addr = bbase + (uint32_t)((wn + browB + 16 * jr) * 128)
                              + (((uint32_t)((ks * 2 + bcoB) * 16)) ^ swz);
                LDSM4(bf[2*jr][0], bf[2*jr][1], bf[2*jr+1][0], bf[2*jr+1][1], addr);
            }
#pragma unroll
            for (int i = 0; i < 4; i++) {
                uint32_t a[4];
                uint32_t addr = abase + (uint32_t)((wm + 16 * i + lrowA) * 128)
                              + (((uint32_t)((ks * 2 + coffA) * 16)) ^ swz);
                LDSM4(a[0], a[1], a[2], a[3], addr);
#pragma unroll
                for (int j = 0; j < 8; j++)
                    mma_f16a(acc[i][j], a, bf[j]);
            }
        }
        __syncthreads();
    }

#pragma unroll
    for (int i = 0; i < 4; i++) {
        const int m = m0 + wm + 16 * i + g;
        float inv0 = 1.f, inv1 = 1.f;
        if (MODE == 2) {
            inv0 = g_rinv[(size_t)bz * NTOK + m];
            inv1 = g_rinv[(size_t)bz * NTOK + m + 8];
        }
#pragma unroll
        for (int j = 0; j < 8; j++) {
            const int n = n0 + wn + 8 * j + 2 * tg;
            uint32_t o0 = acc[i][j][0], o1 = acc[i][j][1];
            if (MODE == 1) {
                float2 f0 = __half22float2(bits_h2(o0));
                float2 f1 = __half22float2(bits_h2(o1));
                o0 = h2_bits(__floats2half2_rn(__expf(f0.x - EXPOFF), __expf(f0.y - EXPOFF)));
                o1 = h2_bits(__floats2half2_rn(__expf(f1.x - EXPOFF), __expf(f1.y - EXPOFF)));
            }
            if (MODE == 2) {
                float2 f0 = __half22float2(bits_h2(o0));
                float2 f1 = __half22float2(bits_h2(o1));
                o0 = h2_bits(__floats2half2_rn(f0.x * inv0, f0.y * inv0));
                o1 = h2_bits(__floats2half2_rn(f1.x * inv1, f1.y * inv1));
            }
            *reinterpret_cast<uint32_t*>(&C[(size_t)m * LDC + n])       = o0;
            *reinterpret_cast<uint32_t*>(&C[(size_t)(m + 8) * LDC + n]) = o1;
        }
    }
}

// ---------------------------------------------------------------
extern "C" void kernel_launch(void* const* d_in, const int* in_sizes, int n_in,
                              void* d_out, int out_size)
{
    const float* x    = (const float*)d_in[0];
    const float* gn_w = (const float*)d_in[1];
    const float* gn_b = (const float*)d_in[2];
    const float* wq   = (const float*)d_in[3];
    const float* bq   = (const float*)d_in[4];
    const float* wk   = (const float*)d_in[5];
    const float* bk   = (const float*)d_in[6];
    const float* wv   = (const float*)d_in[7];
    const float* bv   = (const float*)d_in[8];
    const float* wo   = (const float*)d_in[9];
    const float* bo   = (const float*)d_in[10];
    float* out = (float*)d_out;

    __half *hn, *q, *k, *vt, *o, *p, *w16;
    cudaGetSymbolAddress((void**)&hn, g_hn);
    cudaGetSymbolAddress((void**)&q,  g_q);
    cudaGetSymbolAddress((void**)&k,  g_k);
    cudaGetSymbolAddress((void**)&vt, g_vt);
    cudaGetSymbolAddress((void**)&o,  g_o);
    cudaGetSymbolAddress((void**)&p,  g_p);
    cudaGetSymbolAddress((void**)&w16, g_w16);
    const __half* wo16 = w16 + 3 * (size_t)CCH * CCH;

    const size_t sTok = (size_t)NTOK * CCH;
    const size_t sChn = (size_t)CCH * NTOK;
    const size_t sAtt = (size_t)NTOK * NTOK;
    const float att_scale = 1.0f / sqrtf((float)CCH);

    cudaFuncSetAttribute(qkv_gemm, cudaFuncAttributeMaxDynamicSharedMemorySize, DSMEM);
    cudaFuncSetAttribute(f16acc_gemm<CCH, NTOK, 1>, cudaFuncAttributeMaxDynamicSharedMemorySize, DSMEM_S);
    cudaFuncSetAttribute(f16acc_gemm<NTOK, CCH, 2>, cudaFuncAttributeMaxDynamicSharedMemorySize, DSMEM_S);
    cudaFuncSetAttribute(hgemm<2, 0>, cudaFuncAttributeMaxDynamicSharedMemorySize, DSMEM);

    // 0) weights -> fp16
    convw_kernel<<<dim3(CCH * CCH / 1024, 4), 256>>>(wq, wk, wv, wo);

    // 1) GroupNorm stats + apply/transpose -> g_hn [b, n, c] fp16
    gnstat_kernel<<<BATCH * GRP, 1024>>>(x);
    gnapply_kernel<<<dim3(NTOK / 64, CCH / 64, BATCH), 256>>>(x, gn_w, gn_b);

    // 2) fused QKV (V transposed; Q pre-scaled by att_scale)
    qkv_gemm<<<dim3(6, NTOK / BM, BATCH), 256, DSMEM>>>(hn, bq, bk, bv, q, k, vt,
                                                        att_scale);

    // 3) P~ = exp(Q K^T - 5)   (fp16 accumulate, exp fused in epilogue)
    f16acc_gemm<CCH, NTOK, 1><<<dim3(NTOK / SBN, NTOK / SBM, BATCH), 128, DSMEM_S>>>(
        q, k, p, sTok, sTok, sAtt);

    // 4) row sums -> 1/sum
    rowsum_kernel<<<BATCH * NTOK, 256>>>();

    // 5) O = (P~ V) * rinv[m]  (fp16 accumulate, normalization in epilogue)
    f16acc_gemm<NTOK, CCH, 2><<<dim3(CCH / SBN, NTOK / SBM, BATCH), 128, DSMEM_S>>>(
        p, vt, o, sAtt, sChn, sTok);

    // 6) out[b,c,n] = x + bo[c] + wo @ O^T
    hgemm<2, 0><<<dim3(NTOK / BN, CCH / BM, BATCH), 256, DSMEM>>>(
        wo16, o, out, CCH, NTOK, CCH, 0, sTok, sChn, bo, x, sChn, 1.0f);
}

// round 17
// speedup vs baseline: 1.1182x; 1.0690x over previous
#include <cuda_runtime.h>
#include <cuda_fp16.h>
#include <math.h>
#include <stdint.h>

#define BATCH 2
#define CCH   512
#define NTOK  4096
#define GRP   32
#define CPG   (CCH / GRP)
#define EPSV  1e-6f
#define EXPOFF 5.0f

// fp32-acc GEMM tiling (proj)
#define BM 128
#define BN 256
#define BK 128
#define A_BYTES (BM * BK * 2)
#define B_BYTES (BN * BK * 2)
#define STAGE_BYTES (A_BYTES + B_BYTES)
#define DSMEM (2 * STAGE_BYTES)        // 196608

// 128x128x64 tiling (QKV / S / PV): 4 warps, 2 CTAs/SM
#define SBM 128
#define SBN 128
#define SBK 64
#define SA_BYTES (SBM * SBK * 2)
#define SB_BYTES (SBN * SBK * 2)
#define SSTAGE (SA_BYTES + SB_BYTES)
#define DSMEM_S (3 * SSTAGE)            // 98304

// -------- scratch (__device__ globals; no allocation allowed) --------
__device__ __half g_hn[(size_t)BATCH * NTOK * CCH];   // GN out, TRANSPOSED [b, n, c]
__device__ __half g_q [(size_t)BATCH * NTOK * CCH];   // pre-scaled by att_scale
__device__ __half g_k [(size_t)BATCH * NTOK * CCH];
__device__ __half g_vt[(size_t)BATCH * CCH * NTOK];   // V TRANSPOSED [b, c, n]
__device__ __half g_o [(size_t)BATCH * NTOK * CCH];
__device__ __half g_p [(size_t)BATCH * NTOK * NTOK];  // exp(S-5) (fp16)
__device__ __half g_w16[4 * (size_t)CCH * CCH];
__device__ float  g_gnstat[BATCH * GRP * 2];          // mu, rstd per (b, g)
__device__ float  g_rsum[(size_t)BATCH * NTOK];       // rowsum of exp (atomic)

// ---------------- helpers ----------------
__device__ __forceinline__ uint32_t smem_u32(const void* p) {
    uint32_t a;
    asm("{ .reg .u64 t; cvta.to.shared.u64 t, %1; cvt.u32.u64 %0, t; }"
        : "=r"(a) : "l"(p));
    return a;
}
__device__ __forceinline__ void cp16(void* dst, const void* src) {
    uint32_t d = smem_u32(dst);
    asm volatile("cp.async.cg.shared.global [%0], [%1], 16;" :: "r"(d), "l"(src));
}
#define CP_COMMIT() asm volatile("cp.async.commit_group;")

#define LDSM4(r0, r1, r2, r3, addr) \
    asm volatile("ldmatrix.sync.aligned.m8n8.x4.shared.b16 {%0,%1,%2,%3}, [%4];" \
        : "=r"(r0), "=r"(r1), "=r"(r2), "=r"(r3) : "r"(addr))

__device__ __forceinline__ void mma_f16(float* d, const uint32_t* a, const uint32_t* b) {
    asm volatile(
        "mma.sync.aligned.m16n8k16.row.col.f32.f16.f16.f32 "
        "{%0,%1,%2,%3},{%4,%5,%6,%7},{%8,%9},{%0,%1,%2,%3};"
        : "+f"(d[0]), "+f"(d[1]), "+f"(d[2]), "+f"(d[3])
        : "r"(a[0]), "r"(a[1]), "r"(a[2]), "r"(a[3]), "r"(b[0]), "r"(b[1]));
}
__device__ __forceinline__ void mma_f16a(uint32_t* d, const uint32_t* a, const uint32_t* b) {
    asm volatile(
        "mma.sync.aligned.m16n8k16.row.col.f16.f16.f16.f16 "
        "{%0,%1},{%2,%3,%4,%5},{%6,%7},{%0,%1};"
        : "+r"(d[0]), "+r"(d[1])
        : "r"(a[0]), "r"(a[1]), "r"(a[2]), "r"(a[3]), "r"(b[0]), "r"(b[1]));
}

__device__ __forceinline__ uint32_t h2_bits(__half2 h) {
    uint32_t u; memcpy(&u, &h, 4); return u;
}
__device__ __forceinline__ __half2 bits_h2(uint32_t u) {
    __half2 h; memcpy(&h, &u, 4); return h;
}

// ---------------------------------------------------------------
__global__ void convw_kernel(const float* __restrict__ a, const float* __restrict__ b,
                             const float* __restrict__ c, const float* __restrict__ d)
{
    const float* srcs[4] = {a, b, c, d};
    const float* src = srcs[blockIdx.y];
    __half* dst = g_w16 + (size_t)blockIdx.y * CCH * CCH;
    int i = (blockIdx.x * 256 + threadIdx.x) * 4;
    float4 v = *reinterpret_cast<const float4*>(&src[i]);
    *reinterpret_cast<__half2*>(&dst[i])     = __floats2half2_rn(v.x, v.y);
    *reinterpret_cast<__half2*>(&dst[i + 2]) = __floats2half2_rn(v.z, v.w);
}

// ---------------------------------------------------------------
__global__ void gnstat_kernel(const float* __restrict__ x)
{
    const int bg = blockIdx.x;
    const int NE = CPG * NTOK;
    const size_t base = (size_t)bg * NE;
    const int t = threadIdx.x;

    float s = 0.f, ss = 0.f;
    for (int i = t * 4; i < NE; i += 4096) {
        float4 v = *reinterpret_cast<const float4*>(&x[base + i]);
        s  += v.x + v.y + v.z + v.w;
        ss += v.x * v.x + v.y * v.y + v.z * v.z + v.w * v.w;
    }
    __shared__ float sh[1024], sh2[1024];
    sh[t] = s; sh2[t] = ss;
    __syncthreads();
    for (int o = 512; o > 0; o >>= 1) {
        if (t < o) { sh[t] += sh[t + o]; sh2[t] += sh2[t + o]; }
        __syncthreads();
    }
    if (t == 0) {
        const float mu  = sh[0] / (float)NE;
        const float var = sh2[0] / (float)NE - mu * mu;
        g_gnstat[bg * 2]     = mu;
        g_gnstat[bg * 2 + 1] = rsqrtf(var + EPSV);
    }
}

// ---------------------------------------------------------------
__global__ void gnapply_kernel(const float* __restrict__ x,
                               const float* __restrict__ w,
                               const float* __restrict__ b)
{
    __shared__ float ts[64][65];
    __shared__ float ssc[64], ssb[64];
    const int n0 = blockIdx.x * 64;
    const int c0 = blockIdx.y * 64;
    const int bb = blockIdx.z;
    const int t = threadIdx.x;
    const size_t xbase = (size_t)bb * CCH * NTOK;

    if (t < 64) {
        const int c = c0 + t;
        const int bg = bb * GRP + c / CPG;
        const float mu   = g_gnstat[bg * 2];
        const float rstd = g_gnstat[bg * 2 + 1];
        const float sc = rstd * w[c];
        ssc[t] = sc;
        ssb[t] = b[c] - mu * sc;
    }
    __syncthreads();

    {
        const int ci = t >> 6;
        const int nj = t & 63;
#pragma unroll
        for (int r = 0; r < 16; r++) {
            const int c = ci + r * 4;
            ts[c][nj] = x[xbase + (size_t)(c0 + c) * NTOK + n0 + nj];
        }
    }
    __syncthreads();

    {
        const int n = t >> 2;
        const int cp = (t & 3) * 16;
        __half hv[16];
#pragma unroll
        for (int i = 0; i < 16; i++)
            hv[i] = __float2half_rn(ts[cp + i][n] * ssc[cp + i] + ssb[cp + i]);
        __half* dst = g_hn + (size_t)bb * NTOK * CCH + (size_t)(n0 + n) * CCH + c0 + cp;
        *reinterpret_cast<uint4*>(dst) = *reinterpret_cast<uint4*>(hv);
        *reinterpret_cast<uint4*>(dst + 8) = *reinterpret_cast<uint4*>(hv + 8);
    }
}

// ---------------------------------------------------------------
// fp32-acc fp16 GEMM body (proj): CTA 128x256x128, 2-stage,
// 8 warps (2m x 4n), warp 64x64, fragment double-buffer pipeline.
// EPI 2 only: acc + bias[m] + resid, fp32 out.
// ---------------------------------------------------------------
__device__ __forceinline__ void proj_body(
    char* smem, const __half* __restrict__ A, const __half* __restrict__ B,
    float* __restrict__ C, int M, int Nn, int K, int m0, int n0,
    const float* __restrict__ bias, const float* __restrict__ resid)
{
    const uint32_t sbase = smem_u32(smem);
    const int tid = threadIdx.x, wid = tid >> 5, lane = tid & 31;
    const int wm = (wid & 1) * 64;
    const int wn = (wid >> 1) * 64;
    const int g = lane >> 2, tg = lane & 3;

    float acc[4][8][4] = {};

    auto stage = [&](int buf, int k0) {
        char* da = smem + buf * STAGE_BYTES;
        char* db = da + A_BYTES;
#pragma unroll
        for (int i = 0; i < 8; i++) {
            int cid = tid + i * 256;
            int r = cid >> 4, c = cid & 15;
            uint32_t off = (uint32_t)(r * 256 + c * 16) ^ (uint32_t)((r & 7) << 4);
            cp16(da + off, A + (size_t)(m0 + r) * K + k0 + c * 8);
        }
#pragma unroll
        for (int i = 0; i < 16; i++) {
            int cid = tid + i * 256;
            int r = cid >> 4, c = cid & 15;
            uint32_t off = (uint32_t)(r * 256 + c * 16) ^ (uint32_t)((r & 7) << 4);
            cp16(db + off, B + (size_t)(n0 + r) * K + k0 + c * 8);
        }
    };

    const int lrowA = lane & 15;
    const int coffA = lane >> 4;
    const int browB = ((lane >> 4) << 3) + (lane & 7);
    const int bcoB  = (lane >> 3) & 1;
    const uint32_t swz = (uint32_t)((lane & 7) << 4);

    const int KT = K / BK;
    stage(0, 0);  CP_COMMIT();

    for (int kt = 0; kt < KT; kt++) {
        if (kt + 1 < KT) stage((kt + 1) & 1, (kt + 1) * BK);
        CP_COMMIT();
        asm volatile("cp.async.wait_group 1;");
        __syncthreads();

        const uint32_t abase = sbase + (kt & 1) * STAGE_BYTES;
        const uint32_t bbase = abase + A_BYTES;

        uint32_t bf[2][8][2];
        uint32_t a[2][4];

        auto ldB = [&](int buf, int ks) {
#pragma unroll
            for (int jr = 0; jr < 4; jr++) {
                uint32_t addr = bbase + (uint32_t)((wn + browB + 16 * jr) * 256)
                              + (((uint32_t)((ks * 2 + bcoB) * 16)) ^ swz);
                LDSM4(bf[buf][2*jr][0], bf[buf][2*jr][1],
                      bf[buf][2*jr+1][0], bf[buf][2*jr+1][1], addr);
            }
        };
        auto ldA = [&](int buf, int ks, int i) {
            uint32_t addr = abase + (uint32_t)((wm + 16 * i + lrowA) * 256)
                          + (((uint32_t)((ks * 2 + coffA) * 16)) ^ swz);
            LDSM4(a[buf][0], a[buf][1], a[buf][2], a[buf][3], addr);
        };

        ldB(0, 0);
        ldA(0, 0, 0);

#pragma unroll
        for (int ks = 0; ks < 8; ks++) {
#pragma unroll
            for (int i = 0; i < 4; i++) {
                if (i < 3) {
                    ldA((i + 1) & 1, ks, i + 1);
                } else if (ks < 7) {
                    ldB((ks + 1) & 1, ks + 1);
                    ldA(0, ks + 1, 0);
                }
#pragma unroll
                for (int j = 0; j < 8; j++)
                    mma_f16(acc[i][j], a[i & 1], bf[ks & 1][j]);
            }
        }
        __syncthreads();
    }

#pragma unroll
    for (int i = 0; i < 4; i++) {
        const int m = m0 + wm + 16 * i + g;
#pragma unroll
        for (int j = 0; j < 8; j++) {
            const int n = n0 + wn + 8 * j + 2 * tg;
            const float* r0 = resid + (size_t)m * Nn + n;
            const float* r1 = resid + (size_t)(m + 8) * Nn + n;
            float v0 = acc[i][j][0] + bias[m] + r0[0];
            float v1 = acc[i][j][1] + bias[m] + r0[1];
            float v2 = acc[i][j][2] + bias[m + 8] + r1[0];
            float v3 = acc[i][j][3] + bias[m + 8] + r1[1];
            *reinterpret_cast<float2*>(&C[(size_t)m * Nn + n])       = make_float2(v0, v1);
            *reinterpret_cast<float2*>(&C[(size_t)(m + 8) * Nn + n]) = make_float2(v2, v3);
        }
    }
}

__global__ void __launch_bounds__(256, 1)
proj_gemm(const __half* __restrict__ A, const __half* __restrict__ B,
          float* __restrict__ C, size_t sB, size_t sC,
          const float* __restrict__ bias, const float* __restrict__ resid, size_t sR)
{
    extern __shared__ __align__(1024) char smem[];
    const int bz = blockIdx.z;
    proj_body(smem, A, B + (size_t)bz * sB, C + (size_t)bz * sC,
              CCH, NTOK, CCH, blockIdx.y * BM, blockIdx.x * BN,
              bias, resid + (size_t)bz * sR);
}

// ---------------------------------------------------------------
// QKV GEMM: fp32 acc, CTA 128x128x64, 4 warps (2m x 2n), warp 64x64,
// 3-stage ring, 2 CTAs/SM. K = CCH compile-time.
// grid: (CCH/128, NTOK/128, 3*BATCH); z = p*BATCH + bb.
// p<2: fp16 out (Q scaled); p==2: fp16 transposed out (V^T).
// ---------------------------------------------------------------
__global__ void __launch_bounds__(128, 2)
qkv_gemm(const __half* __restrict__ hn,
         const float* __restrict__ bq, const float* __restrict__ bk,
         const float* __restrict__ bv,
         __half* __restrict__ q, __half* __restrict__ k, __half* __restrict__ v,
         float att_scale)
{
    extern __shared__ __align__(1024) char smem[];
    const uint32_t sbase = smem_u32(smem);
    const int tid = threadIdx.x, wid = tid >> 5, lane = tid & 31;
    const int p  = blockIdx.z / BATCH;
    const int bb = blockIdx.z % BATCH;
    const size_t sTok = (size_t)NTOK * CCH;
    const size_t sChn = (size_t)CCH * NTOK;
    const __half* W  = g_w16 + (size_t)p * CCH * CCH;
    const float* bias = (p == 0) ? bq : (p == 1) ? bk : bv;
    const __half* A  = hn + (size_t)bb * sTok;
    const int m0 = blockIdx.y * SBM, n0 = blockIdx.x * SBN;
    const float sc = (p == 0) ? att_scale : 1.0f;
    const int wm = (wid & 1) * 64;
    const int wn = (wid >> 1) * 64;
    const int g = lane >> 2, tg = lane & 3;

    float acc[4][8][4] = {};

    auto stage = [&](int buf, int k0) {
        char* da = smem + buf * SSTAGE;
        char* db = da + SA_BYTES;
#pragma unroll
        for (int i = 0; i < 8; i++) {
            int cid = tid + i * 128;
            int r = cid >> 3, c = cid & 7;
            uint32_t off = (uint32_t)(r * 128 + c * 16) ^ (uint32_t)((r & 7) << 4);
            cp16(da + off, A + (size_t)(m0 + r) * CCH + k0 + c * 8);
        }
#pragma unroll
        for (int i = 0; i < 8; i++) {
            int cid = tid + i * 128;
            int r = cid >> 3, c = cid & 7;
            uint32_t off = (uint32_t)(r * 128 + c * 16) ^ (uint32_t)((r & 7) << 4);
            cp16(db + off, W + (size_t)(n0 + r) * CCH + k0 + c * 8);
        }
    };

    const int lrowA = lane & 15;
    const int coffA = lane >> 4;
    const int browB = ((lane >> 4) << 3) + (lane & 7);
    const int bcoB  = (lane >> 3) & 1;
    const uint32_t swz = (uint32_t)((lane & 7) << 4);

    constexpr int KT = CCH / SBK;
    stage(0, 0);    CP_COMMIT();
    stage(1, SBK);  CP_COMMIT();

#pragma unroll 1
    for (int kt = 0; kt < KT; kt++) {
        asm volatile("cp.async.wait_group 1;");
        __syncthreads();
        if (kt + 2 < KT) stage((kt + 2) % 3, (kt + 2) * SBK);
        CP_COMMIT();

        const uint32_t abase = sbase + (kt % 3) * SSTAGE;
        const uint32_t bbase = abase + SA_BYTES;

#pragma unroll
        for (int ks = 0; ks < 4; ks++) {
            uint32_t bf[8][2];
#pragma unroll
            for (int jr = 0; jr < 4; jr++) {
                uint32_t addr = bbase + (uint32_t)((wn + browB + 16 * jr) * 128)
                              + (((uint32_t)((ks * 2 + bcoB) * 16)) ^ swz);
                LDSM4(bf[2*jr][0], bf[2*jr][1], bf[2*jr+1][0], bf[2*jr+1][1], addr);
            }
#pragma unroll
            for (int i = 0; i < 4; i++) {
                uint32_t a[4];
                uint32_t addr = abase + (uint32_t)((wm + 16 * i + lrowA) * 128)
                              + (((uint32_t)((ks * 2 + coffA) * 16)) ^ swz);
                LDSM4(a[0], a[1], a[2], a[3], addr);
#pragma unroll
                for (int j = 0; j < 8; j++)
                    mma_f16(acc[i][j], a, bf[j]);
            }
        }
        __syncthreads();
    }

    if (p < 2) {
        __half* C = ((p == 0) ? q : k) + (size_t)bb * sTok;
#pragma unroll
        for (int i = 0; i < 4; i++) {
            const int m = m0 + wm + 16 * i + g;
#pragma unroll
            for (int j = 0; j < 8; j++) {
                const int n = n0 + wn + 8 * j + 2 * tg;
                float v0 = (acc[i][j][0] + bias[n]) * sc;
                float v1 = (acc[i][j][1] + bias[n + 1]) * sc;
                float v2 = (acc[i][j][2] + bias[n]) * sc;
                float v3 = (acc[i][j][3] + bias[n + 1]) * sc;
                *reinterpret_cast<__half2*>(&C[(size_t)m * CCH + n])       = __floats2half2_rn(v0, v1);
                *reinterpret_cast<__half2*>(&C[(size_t)(m + 8) * CCH + n]) = __floats2half2_rn(v2, v3);
            }
        }
    } else {
        __half* C = v + (size_t)bb * sChn;
        __syncthreads();
        char* tp = smem + wid * 8192;    // 64n x 128B(m)
#pragma unroll
        for (int i = 0; i < 4; i++) {
#pragma unroll
            for (int j = 0; j < 8; j++) {
                const int nl = 8 * j + 2 * tg;
                const int nch = n0 + wn + nl;
                float v0 = acc[i][j][0] + bias[nch];
                float v1 = acc[i][j][1] + bias[nch + 1];
                float v2 = acc[i][j][2] + bias[nch];
                float v3 = acc[i][j][3] + bias[nch + 1];
                const int ml0 = 16 * i + g, ml1 = ml0 + 8;
                auto put = [&](int nn, int mm, float vv) {
                    uint32_t o = (uint32_t)(nn * 128 + ((((mm >> 3) ^ (nn & 7)) << 4)) + (mm & 7) * 2);
                    *reinterpret_cast<__half*>(tp + o) = __float2half_rn(vv);
                };
                put(nl,     ml0, v0); put(nl + 1, ml0, v1);
                put(nl,     ml1, v2); put(nl + 1, ml1, v3);
            }
        }
        __syncwarp();
#pragma unroll
        for (int r = 0; r < 64; r++) {
            uint32_t o = (uint32_t)(r * 128 + (((lane >> 2) ^ (r & 7)) << 4) + (lane & 3) * 4);
            uint32_t vv = *reinterpret_cast<uint32_t*>(tp + o);
            *reinterpret_cast<uint32_t*>(&C[(size_t)(n0 + wn + r) * NTOK + m0 + wm + lane * 2]) = vv;
        }
    }
}

// ---------------------------------------------------------------
// fp16-accumulate GEMM (S / PV), compile-time K and LDC.
// MODE 1: store exp(acc - EXPOFF), atomicAdd row sums to g_rsum.
// MODE 2: store acc / g_rsum[batch*NTOK + m]  (PV normalization).
// CTA 128x128x64, 128 thr (4 warps, 2m x 2n), warp 64x64.
// ---------------------------------------------------------------
template<int K, int LDC, int MODE>
__global__ void __launch_bounds__(128, 2)
f16acc_gemm(const __half* __restrict__ Ag, const __half* __restrict__ Bg,
            __half* __restrict__ Cg, size_t sA, size_t sB, size_t sC)
{
    extern __shared__ __align__(1024) char smem[];
    const uint32_t sbase = smem_u32(smem);
    const int tid = threadIdx.x, wid = tid >> 5, lane = tid & 31;
    const int bz = blockIdx.z;
    const __half* A = Ag + (size_t)bz * sA;
    const __half* B = Bg + (size_t)bz * sB;
    __half* C = Cg + (size_t)bz * sC;
    const int m0 = blockIdx.y * SBM, n0 = blockIdx.x * SBN;
    const int wm = (wid & 1) * 64;
    const int wn = (wid >> 1) * 64;
    const int g = lane >> 2, tg = lane & 3;

    uint32_t acc[4][8][2] = {};

    auto stage = [&](int buf, int k0) {
        char* da = smem + buf * SSTAGE;
        char* db = da + SA_BYTES;
#pragma unroll
        for (int i = 0; i < 8; i++) {
            int cid = tid + i * 128;
            int r = cid >> 3, c = cid & 7;
            uint32_t off = (uint32_t)(r * 128 + c * 16) ^ (uint32_t)((r & 7) << 4);
            cp16(da + off, A + (size_t)(m0 + r) * K + k0 + c * 8);
        }
#pragma unroll
        for (int i = 0; i < 8; i++) {
            int cid = tid + i * 128;
            int r = cid >> 3, c = cid & 7;
            uint32_t off = (uint32_t)(r * 128 + c * 16) ^ (uint32_t)((r & 7) << 4);
            cp16(db + off, B + (size_t)(n0 + r) * K + k0 + c * 8);
        }
    };

    const int lrowA = lane & 15;
    const int coffA = lane >> 4;
    const int browB = ((lane >> 4) << 3) + (lane & 7);
    const int bcoB  = (lane >> 3) & 1;
    const uint32_t swz = (uint32_t)((lane & 7) << 4);

    constexpr int KT = K / SBK;
    stage(0, 0);    CP_COMMIT();
    stage(1, SBK);  CP_COMMIT();

#pragma unroll 1
    for (int kt = 0; kt < KT; kt++) {
        asm volatile("cp.async.wait_group 1;");
        __syncthreads();
        if (kt + 2 < KT) stage((kt + 2) % 3, (kt + 2) * SBK);
        CP_COMMIT();

        const uint32_t abase = sbase + (kt % 3) * SSTAGE;
        const uint32_t bbase = abase + SA_BYTES;

#pragma unroll
        for (int ks = 0; ks < 4; ks++) {
            uint32_t bf[8][2];
#pragma unroll
            for (int jr = 0; jr < 4; jr++) {
                uint32_t addr = bbase + (uint32_t)((wn + browB + 16 * jr) * 128)
                              + (((uint32_t)((ks * 2 + bcoB) * 16)) ^ swz);
                LDSM4(bf[2*jr][0], bf[2*jr][1], bf[2*jr+1][0], bf[2*jr+1][1], addr);
            }
#pragma unroll
            for (int i = 0; i < 4; i++) {
                uint32_t a[4];
                uint32_t addr = abase + (uint32_t)((wm + 16 * i + lrowA) * 128)
                              + (((uint32_t)((ks * 2 + coffA) * 16)) ^ swz);
                LDSM4(a[0], a[1], a[2], a[3], addr);
#pragma unroll
                for (int j = 0; j < 8; j++)
                    mma_f16a(acc[i][j], a, bf[j]);
            }
        }
        __syncthreads();
    }

#pragma unroll
    for (int i = 0; i < 4; i++) {
        const int m = m0 + wm + 16 * i + g;
        float inv0 = 1.f, inv1 = 1.f;
        if (MODE == 2) {
            inv0 = __fdividef(1.0f, g_rsum[(size_t)bz * NTOK + m]);
            inv1 = __fdividef(1.0f, g_rsum[(size_t)bz * NTOK + m + 8]);
        }
        float rs0 = 0.f, rs1 = 0.f;
#pragma unroll
        for (int j = 0; j < 8; j++) {
            const int n = n0 + wn + 8 * j + 2 * tg;
            uint32_t o0 = acc[i][j][0], o1 = acc[i][j][1];
            if (MODE == 1) {
                float2 f0 = __half22float2(bits_h2(o0));
                float2 f1 = __half22float2(bits_h2(o1));
                float e0 = __expf(f0.x - EXPOFF), e1 = __expf(f0.y - EXPOFF);
                float e2 = __expf(f1.x - EXPOFF), e3 = __expf(f1.y - EXPOFF);
                rs0 += e0 + e1;
                rs1 += e2 + e3;
                o0 = h2_bits(__floats2half2_rn(e0, e1));
                o1 = h2_bits(__floats2half2_rn(e2, e3));
            }
            if (MODE == 2) {
                float2 f0 = __half22float2(bits_h2(o0));
                float2 f1 = __half22float2(bits_h2(o1));
                o0 = h2_bits(__floats2half2_rn(f0.x * inv0, f0.y * inv0));
                o1 = h2_bits(__floats2half2_rn(f1.x * inv1, f1.y * inv1));
            }
            *reinterpret_cast<uint32_t*>(&C[(size_t)m * LDC + n])       = o0;
            *reinterpret_cast<uint32_t*>(&C[(size_t)(m + 8) * LDC + n]) = o1;
        }
        if (MODE == 1) {
            rs0 += __shfl_xor_sync(0xFFFFFFFF, rs0, 1);
            rs0 += __shfl_xor_sync(0xFFFFFFFF, rs0, 2);
            rs1 += __shfl_xor_sync(0xFFFFFFFF, rs1, 1);
            rs1 += __shfl_xor_sync(0xFFFFFFFF, rs1, 2);
            if (tg == 0) {
                atomicAdd(&g_rsum[(size_t)bz * NTOK + m], rs0);
                atomicAdd(&g_rsum[(size_t)bz * NTOK + m + 8], rs1);
            }
        }
    }
}

// ---------------------------------------------------------------
extern "C" void kernel_launch(void* const* d_in, const int* in_sizes, int n_in,
                              void* d_out, int out_size)
{
    const float* x    = (const float*)d_in[0];
    const float* gn_w = (const float*)d_in[1];
    const float* gn_b = (const float*)d_in[2];
    const float* wq   = (const float*)d_in[3];
    const float* bq   = (const float*)d_in[4];
    const float* wk   = (const float*)d_in[5];
    const float* bk   = (const float*)d_in[6];
    const float* wv   = (const float*)d_in[7];
    const float* bv   = (const float*)d_in[8];
    const float* wo   = (const float*)d_in[9];
    const float* bo   = (const float*)d_in[10];
    float* out = (float*)d_out;

    __half *hn, *q, *k, *vt, *o, *p, *w16;
    float* rsum;
    cudaGetSymbolAddress((void**)&hn, g_hn);
    cudaGetSymbolAddress((void**)&q,  g_q);
    cudaGetSymbolAddress((void**)&k,  g_k);
    cudaGetSymbolAddress((void**)&vt, g_vt);
    cudaGetSymbolAddress((void**)&o,  g_o);
    cudaGetSymbolAddress((void**)&p,  g_p);
    cudaGetSymbolAddress((void**)&w16, g_w16);
    cudaGetSymbolAddress((void**)&rsum, g_rsum);
    const __half* wo16 = w16 + 3 * (size_t)CCH * CCH;

    const size_t sTok = (size_t)NTOK * CCH;
    const size_t sChn = (size_t)CCH * NTOK;
    const size_t sAtt = (size_t)NTOK * NTOK;
    const float att_scale = 1.0f / sqrtf((float)CCH);

    cudaFuncSetAttribute(qkv_gemm, cudaFuncAttributeMaxDynamicSharedMemorySize, DSMEM_S);
    cudaFuncSetAttribute(f16acc_gemm<CCH, NTOK, 1>, cudaFuncAttributeMaxDynamicSharedMemorySize, DSMEM_S);
    cudaFuncSetAttribute(f16acc_gemm<NTOK, CCH, 2>, cudaFuncAttributeMaxDynamicSharedMemorySize, DSMEM_S);
    cudaFuncSetAttribute(proj_gemm, cudaFuncAttributeMaxDynamicSharedMemorySize, DSMEM);

    // 0) weights -> fp16; zero row sums
    convw_kernel<<<dim3(CCH * CCH / 1024, 4), 256>>>(wq, wk, wv, wo);
    cudaMemsetAsync(rsum, 0, (size_t)BATCH * NTOK * sizeof(float));

    // 1) GroupNorm stats + apply/transpose -> g_hn [b, n, c] fp16
    gnstat_kernel<<<BATCH * GRP, 1024>>>(x);
    gnapply_kernel<<<dim3(NTOK / 64, CCH / 64, BATCH), 256>>>(x, gn_w, gn_b);

    // 2) fused QKV (V transposed; Q pre-scaled), 2 CTAs/SM shape
    qkv_gemm<<<dim3(CCH / SBN, NTOK / SBM, 3 * BATCH), 128, DSMEM_S>>>(
        hn, bq, bk, bv, q, k, vt, att_scale);

    // 3) P~ = exp(Q K^T - 5); row sums accumulated atomically
    f16acc_gemm<CCH, NTOK, 1><<<dim3(NTOK / SBN, NTOK / SBM, BATCH), 128, DSMEM_S>>>(
        q, k, p, sTok, sTok, sAtt);

    // 4) O = (P~ V) / rsum[m]
    f16acc_gemm<NTOK, CCH, 2><<<dim3(CCH / SBN, NTOK / SBM, BATCH), 128, DSMEM_S>>>(
        p, vt, o, sAtt, sChn, sTok);

    // 5) out[b,c,n] = x + bo[c] + wo @ O^T
    proj_gemm<<<dim3(NTOK / BN, CCH / BM, BATCH), 256, DSMEM>>>(
        wo16, o, out, sTok, sChn, bo, x, sChn);
}